// round 1
// baseline (speedup 1.0000x reference)
#include <cuda_runtime.h>
#include <math.h>

// Problem constants
#define Bc   4
#define Nc   8192
#define Dc   512
#define Hc   8
#define DHc  64
#define Kc   64
#define HIDc 1024
#define Mrows (Bc*Nc)        // 32768
#define MH    (Mrows*Hc)     // 262144 token-heads
#define SEGc  16             // N-segments for dispatch reduction
#define SEGLEN (Nc/SEGc)     // 512

// Scratch (device globals; no allocation allowed)
__device__ float g_xm   [(size_t)Mrows*Dc];       // [B,N,H*DH] 64MB
__device__ float g_t1   [(size_t)MH*Kc];          // gelu(xm@tw1+tb1) 64MB
__device__ float g_logit[(size_t)MH*Kc];          // xm@Wsl+bsl 64MB
__device__ float g_sw   [(size_t)MH*Kc];          // softmax weights [B,N,H,K] 64MB
__device__ float g_stp  [Bc*Hc*SEGc*Kc*DHc];      // dispatch partials 8MB
__device__ float g_snp  [Bc*Hc*SEGc*Kc];          // snorm partials
__device__ float g_st   [Bc*Hc*Kc*DHc];           // slice tokens
__device__ float g_ost  [Bc*Hc*Kc*DHc];           // attn output slice tokens
__device__ float g_y    [(size_t)Mrows*Dc];       // scatter-back 64MB
__device__ float g_o2   [(size_t)Mrows*Dc];       // after Wp + residual 64MB
__device__ float g_ln   [(size_t)Mrows*Dc];       // layernorm out 64MB
__device__ float g_mid  [(size_t)Mrows*HIDc];     // gelu(h@W1+b1) 128MB

__device__ __forceinline__ float gelu_f(float x) {
    return 0.5f * x * (1.0f + erff(0.70710678118654752440f * x));
}

// ---------------------------------------------------------------------------
// Generic tiled fp32 GEMM: C[M,Nd] = A[M,Kd] @ B[Kd,Nd] (+bias[col]) epilogue
// EPI: 0 = +bias, 1 = +bias+res[row,col], 2 = gelu(+bias)
// M%64==0, Kd%16==0, Nd%64==0 assumed.
// ---------------------------------------------------------------------------
template<int EPI>
__global__ __launch_bounds__(256) void gemm_k(
    const float* __restrict__ A, const float* __restrict__ Bm,
    const float* __restrict__ bias, const float* __restrict__ res,
    float* __restrict__ C, int Kd, int Nd)
{
    __shared__ float As[16][68];   // [k][m], padded
    __shared__ float Bs[16][64];   // [k][n]
    const int t  = threadIdx.x;
    const int tx = t & 15, ty = t >> 4;
    const int m0 = blockIdx.y << 6;
    const int n0 = blockIdx.x << 6;
    const int ar = t >> 2,  ak = (t & 3) << 2;   // A tile: row, k-offset
    const int br = t >> 4,  bc = (t & 15) << 2;  // B tile: k-row, col-offset
    const float* Aptr = A + (size_t)(m0 + ar) * Kd + ak;
    const float* Bptr = Bm + (size_t)br * Nd + n0 + bc;

    float acc[4][4] = {};
    for (int k0 = 0; k0 < Kd; k0 += 16) {
        float4 av = *(const float4*)(Aptr + k0);
        float4 bv = *(const float4*)(Bptr + (size_t)k0 * Nd);
        As[ak+0][ar] = av.x; As[ak+1][ar] = av.y;
        As[ak+2][ar] = av.z; As[ak+3][ar] = av.w;
        *(float4*)&Bs[br][bc] = bv;
        __syncthreads();
        #pragma unroll
        for (int kk = 0; kk < 16; kk++) {
            float4 a4 = *(const float4*)&As[kk][ty << 2];
            float4 b4 = *(const float4*)&Bs[kk][tx << 2];
            acc[0][0] += a4.x*b4.x; acc[0][1] += a4.x*b4.y; acc[0][2] += a4.x*b4.z; acc[0][3] += a4.x*b4.w;
            acc[1][0] += a4.y*b4.x; acc[1][1] += a4.y*b4.y; acc[1][2] += a4.y*b4.z; acc[1][3] += a4.y*b4.w;
            acc[2][0] += a4.z*b4.x; acc[2][1] += a4.z*b4.y; acc[2][2] += a4.z*b4.z; acc[2][3] += a4.z*b4.w;
            acc[3][0] += a4.w*b4.x; acc[3][1] += a4.w*b4.y; acc[3][2] += a4.w*b4.z; acc[3][3] += a4.w*b4.w;
        }
        __syncthreads();
    }
    const int col = n0 + (tx << 2);
    float4 bb = *(const float4*)&bias[col];
    #pragma unroll
    for (int i = 0; i < 4; i++) {
        int row = m0 + (ty << 2) + i;
        float4 v;
        v.x = acc[i][0] + bb.x; v.y = acc[i][1] + bb.y;
        v.z = acc[i][2] + bb.z; v.w = acc[i][3] + bb.w;
        if (EPI == 2) {
            v.x = gelu_f(v.x); v.y = gelu_f(v.y); v.z = gelu_f(v.z); v.w = gelu_f(v.w);
        }
        if (EPI == 1) {
            float4 r = *(const float4*)&res[(size_t)row * Nd + col];
            v.x += r.x; v.y += r.y; v.z += r.z; v.w += r.w;
        }
        *(float4*)&C[(size_t)row * Nd + col] = v;
    }
}

// ---------------------------------------------------------------------------
// Router softmax: one warp per token-head (row of g_t1/g_logit).
// temp = max(gelu(t1g @ tw2 + tb2) + bias[h], 0.01); sw = softmax((logit+gumbel)/temp)
// ---------------------------------------------------------------------------
__global__ __launch_bounds__(256) void router_softmax(
    const float* __restrict__ tw2, const float* __restrict__ tb2,
    const float* __restrict__ bias, const float* __restrict__ gumbel)
{
    int warp = (blockIdx.x << 3) + (threadIdx.x >> 5);
    int lane = threadIdx.x & 31;
    size_t base = (size_t)warp * 64;
    int h  = warp & 7;
    int bn = warp >> 3;
    int n  = bn & (Nc - 1);
    int b  = bn >> 13;  // /8192

    float t1a = g_t1[base + lane], t1b = g_t1[base + lane + 32];
    float v = t1a * tw2[lane] + t1b * tw2[lane + 32];
    #pragma unroll
    for (int off = 16; off; off >>= 1) v += __shfl_xor_sync(0xffffffffu, v, off);
    float temp = fmaxf(gelu_f(v + tb2[0]) + bias[h], 0.01f);
    float invT = 1.0f / temp;

    size_t gbase = ((((size_t)b * Hc + h) * Nc + n)) * 64;
    float za = (g_logit[base + lane]      + gumbel[gbase + lane])      * invT;
    float zb = (g_logit[base + lane + 32] + gumbel[gbase + lane + 32]) * invT;
    float m = fmaxf(za, zb);
    #pragma unroll
    for (int off = 16; off; off >>= 1) m = fmaxf(m, __shfl_xor_sync(0xffffffffu, m, off));
    float ea = expf(za - m), eb = expf(zb - m);
    float s = ea + eb;
    #pragma unroll
    for (int off = 16; off; off >>= 1) s += __shfl_xor_sync(0xffffffffu, s, off);
    float inv = 1.0f / s;
    g_sw[base + lane]      = ea * inv;
    g_sw[base + lane + 32] = eb * inv;
}

// ---------------------------------------------------------------------------
// Dispatch: st_part[k,c] = sum_{n in seg} sw[n,k]*xm[n,c]; snorm_part[k] = sum sw[n,k]
// grid: (B*H, SEGc), 256 threads, each thread 4x4 of the 64x64 output.
// ---------------------------------------------------------------------------
__global__ __launch_bounds__(256) void dispatch_partial()
{
    int bh = blockIdx.x, s = blockIdx.y;
    int b = bh >> 3, h = bh & 7;
    int t = threadIdx.x;
    int tx = t & 15, ty = t >> 4;
    __shared__ float sws[32][64];
    __shared__ float xms[32][64];
    float acc[4][4] = {};
    float sn = 0.f;
    int nbase = s * SEGLEN;
    for (int ch = 0; ch < SEGLEN; ch += 32) {
        #pragma unroll
        for (int j = 0; j < 8; j++) {
            int idx = t + (j << 8);
            int r = idx >> 6, c = idx & 63;
            size_t nrow = (size_t)(b * Nc + nbase + ch + r);
            xms[r][c] = g_xm[nrow * Dc + h * 64 + c];
            sws[r][c] = g_sw[(nrow * Hc + h) * 64 + c];
        }
        __syncthreads();
        if (t < 64) {
            #pragma unroll
            for (int nn = 0; nn < 32; nn++) sn += sws[nn][t];
        }
        #pragma unroll 4
        for (int nn = 0; nn < 32; nn++) {
            float4 a4 = *(const float4*)&sws[nn][ty << 2];   // k-dim
            float4 b4 = *(const float4*)&xms[nn][tx << 2];   // c-dim
            acc[0][0] += a4.x*b4.x; acc[0][1] += a4.x*b4.y; acc[0][2] += a4.x*b4.z; acc[0][3] += a4.x*b4.w;
            acc[1][0] += a4.y*b4.x; acc[1][1] += a4.y*b4.y; acc[1][2] += a4.y*b4.z; acc[1][3] += a4.y*b4.w;
            acc[2][0] += a4.z*b4.x; acc[2][1] += a4.z*b4.y; acc[2][2] += a4.z*b4.z; acc[2][3] += a4.z*b4.w;
            acc[3][0] += a4.w*b4.x; acc[3][1] += a4.w*b4.y; acc[3][2] += a4.w*b4.z; acc[3][3] += a4.w*b4.w;
        }
        __syncthreads();
    }
    int base = (bh * SEGc + s) * 64;
    #pragma unroll
    for (int i = 0; i < 4; i++)
        #pragma unroll
        for (int j = 0; j < 4; j++)
            g_stp[(size_t)(base + (ty << 2) + i) * 64 + (tx << 2) + j] = acc[i][j];
    if (t < 64) g_snp[base + t] = sn;
}

// Reduce partials: st[k,c] = sum_s part / (snorm[k]+1e-5)
__global__ __launch_bounds__(256) void dispatch_reduce()
{
    int bh = blockIdx.x, t = threadIdx.x;
    __shared__ float sn[64];
    if (t < 64) {
        float v = 1e-5f;
        for (int s = 0; s < SEGc; s++) v += g_snp[(bh * SEGc + s) * 64 + t];
        sn[t] = v;
    }
    __syncthreads();
    #pragma unroll
    for (int e = 0; e < 16; e++) {
        int idx = t + (e << 8);
        float v = 0.f;
        for (int s = 0; s < SEGc; s++) v += g_stp[(size_t)(bh * SEGc + s) * 4096 + idx];
        g_st[(size_t)bh * 4096 + idx] = v / sn[idx >> 6];
    }
}

// ---------------------------------------------------------------------------
// Slice attention per (b,h): q,k,v = st@Wq/Wk/Wv; attn=softmax(qk^T/8); out=attn@v
// ---------------------------------------------------------------------------
__global__ __launch_bounds__(256) void slice_attn(
    const float* __restrict__ Wq, const float* __restrict__ Wk, const float* __restrict__ Wv)
{
    __shared__ float Ash[64][64];  // st -> q -> scores
    __shared__ float Ksh[64][64];
    __shared__ float Vsh[64][64];
    int bh = blockIdx.x, t = threadIdx.x;
    int i = t >> 2, c0 = (t & 3) << 4;  // row, 16-col chunk

    #pragma unroll
    for (int e = 0; e < 16; e++) {
        int idx = t + (e << 8);
        Ash[idx >> 6][idx & 63] = g_st[(size_t)bh * 4096 + idx];
    }
    __syncthreads();

    float qr[16], kr[16], vr[16];
    #pragma unroll
    for (int e = 0; e < 16; e++) { qr[e] = 0.f; kr[e] = 0.f; vr[e] = 0.f; }
    for (int d = 0; d < 64; d++) {
        float sv = Ash[i][d];
        #pragma unroll
        for (int e = 0; e < 16; e++) {
            qr[e] += sv * Wq[d * 64 + c0 + e];
            kr[e] += sv * Wk[d * 64 + c0 + e];
            vr[e] += sv * Wv[d * 64 + c0 + e];
        }
    }
    __syncthreads();
    #pragma unroll
    for (int e = 0; e < 16; e++) { Ash[i][c0+e] = qr[e]; Ksh[i][c0+e] = kr[e]; Vsh[i][c0+e] = vr[e]; }
    __syncthreads();

    float sr[16];
    #pragma unroll
    for (int e = 0; e < 16; e++) {
        float sacc = 0.f;
        for (int d = 0; d < 64; d++) sacc += Ash[i][d] * Ksh[c0 + e][d];
        sr[e] = sacc * 0.125f;
    }
    __syncthreads();
    #pragma unroll
    for (int e = 0; e < 16; e++) Ash[i][c0 + e] = sr[e];
    __syncthreads();

    if (t < 64) {
        float mx = -1e30f;
        for (int j = 0; j < 64; j++) mx = fmaxf(mx, Ash[t][j]);
        float sum = 0.f;
        for (int j = 0; j < 64; j++) { float ee = expf(Ash[t][j] - mx); Ash[t][j] = ee; sum += ee; }
        float inv = 1.f / sum;
        for (int j = 0; j < 64; j++) Ash[t][j] *= inv;
    }
    __syncthreads();

    #pragma unroll
    for (int e = 0; e < 16; e++) {
        float o = 0.f;
        for (int j = 0; j < 64; j++) o += Ash[i][j] * Vsh[j][c0 + e];
        g_ost[(size_t)bh * 4096 + i * 64 + c0 + e] = o;
    }
}

// ---------------------------------------------------------------------------
// Scatter back: y[b,n,h*64+c] = sum_g sw[b,n,h,g] * out_st[b,h,g,c]
// grid: B * (N/32) * H, block 256; 32 tokens per block.
// ---------------------------------------------------------------------------
__global__ __launch_bounds__(256) void scatter_back()
{
    int tile = blockIdx.x;
    int h  = tile & 7;
    int nt = (tile >> 3) & 255;
    int b  = tile >> 11;
    int bh = b * Hc + h;
    int t = threadIdx.x;
    __shared__ float osh[64][64];
    __shared__ float swsh[32][64];
    #pragma unroll
    for (int e = 0; e < 16; e++) {
        int idx = t + (e << 8);
        osh[idx >> 6][idx & 63] = g_ost[(size_t)bh * 4096 + idx];
    }
    #pragma unroll
    for (int e = 0; e < 8; e++) {
        int idx = t + (e << 8);
        int r = idx >> 6, c = idx & 63;
        swsh[r][c] = g_sw[(((size_t)(b * Nc + nt * 32 + r)) * Hc + h) * 64 + c];
    }
    __syncthreads();
    int tt = t >> 3, c0 = (t & 7) << 3;
    float o[8] = {};
    for (int g = 0; g < 64; g++) {
        float swv = swsh[tt][g];
        #pragma unroll
        for (int e = 0; e < 8; e++) o[e] += swv * osh[g][c0 + e];
    }
    int n = nt * 32 + tt;
    #pragma unroll
    for (int e = 0; e < 8; e++)
        g_y[((size_t)(b * Nc + n)) * Dc + h * 64 + c0 + e] = o[e];
}

// ---------------------------------------------------------------------------
// LayerNorm over last dim (512), two-pass, one block (128 thr) per row.
// ---------------------------------------------------------------------------
__global__ __launch_bounds__(128) void ln_k(
    const float* __restrict__ gam, const float* __restrict__ bet)
{
    int row = blockIdx.x, t = threadIdx.x;
    const float4 v = *(const float4*)&g_o2[(size_t)row * Dc + (t << 2)];
    float s = v.x + v.y + v.z + v.w;
    __shared__ float rs[4];
    #pragma unroll
    for (int off = 16; off; off >>= 1) s += __shfl_xor_sync(0xffffffffu, s, off);
    int w = t >> 5;
    if ((t & 31) == 0) rs[w] = s;
    __syncthreads();
    float mean = (rs[0] + rs[1] + rs[2] + rs[3]) * (1.f / 512.f);
    float dx = v.x - mean, dy = v.y - mean, dz = v.z - mean, dw = v.w - mean;
    float q = dx*dx + dy*dy + dz*dz + dw*dw;
    #pragma unroll
    for (int off = 16; off; off >>= 1) q += __shfl_xor_sync(0xffffffffu, q, off);
    __syncthreads();
    if ((t & 31) == 0) rs[w] = q;
    __syncthreads();
    float var = (rs[0] + rs[1] + rs[2] + rs[3]) * (1.f / 512.f);
    float inv = rsqrtf(var + 1e-5f);
    float4 gv = *(const float4*)&gam[t << 2];
    float4 bv = *(const float4*)&bet[t << 2];
    float4 o;
    o.x = dx * inv * gv.x + bv.x;
    o.y = dy * inv * gv.y + bv.y;
    o.z = dz * inv * gv.z + bv.z;
    o.w = dw * inv * gv.w + bv.w;
    *(float4*)&g_ln[(size_t)row * Dc + (t << 2)] = o;
}

// ---------------------------------------------------------------------------
extern "C" void kernel_launch(void* const* d_in, const int* in_sizes, int n_in,
                              void* d_out, int out_size)
{
    const float* x      = (const float*)d_in[0];
    const float* gumbel = (const float*)d_in[1];
    const float* Wx     = (const float*)d_in[2];
    const float* bx     = (const float*)d_in[3];
    const float* tw1    = (const float*)d_in[4];
    const float* tb1    = (const float*)d_in[5];
    const float* tw2    = (const float*)d_in[6];
    const float* tb2    = (const float*)d_in[7];
    const float* bias   = (const float*)d_in[8];
    const float* Wsl    = (const float*)d_in[9];
    const float* bsl    = (const float*)d_in[10];
    const float* Wq     = (const float*)d_in[11];
    const float* Wk     = (const float*)d_in[12];
    const float* Wv     = (const float*)d_in[13];
    const float* Wp     = (const float*)d_in[14];
    const float* bp     = (const float*)d_in[15];
    const float* ln2g   = (const float*)d_in[16];
    const float* ln2b   = (const float*)d_in[17];
    const float* W1     = (const float*)d_in[18];
    const float* b1     = (const float*)d_in[19];
    const float* W2     = (const float*)d_in[20];
    const float* b2     = (const float*)d_in[21];
    float* out = (float*)d_out;

    float *xm, *t1, *lg, *y, *o2, *ln, *mid;
    cudaGetSymbolAddress((void**)&xm,  g_xm);
    cudaGetSymbolAddress((void**)&t1,  g_t1);
    cudaGetSymbolAddress((void**)&lg,  g_logit);
    cudaGetSymbolAddress((void**)&y,   g_y);
    cudaGetSymbolAddress((void**)&o2,  g_o2);
    cudaGetSymbolAddress((void**)&ln,  g_ln);
    cudaGetSymbolAddress((void**)&mid, g_mid);

    // 1. xm = x @ Wx + bx   [32768,512]x[512,512]
    gemm_k<0><<<dim3(Dc/64, Mrows/64), 256>>>(x, Wx, bx, nullptr, xm, Dc, Dc);
    // 2. t1 = gelu(xm_rows @ tw1 + tb1)  viewing xm as [262144,64]
    gemm_k<2><<<dim3(1, MH/64), 256>>>(xm, tw1, tb1, nullptr, t1, 64, 64);
    // 3. logits = xm_rows @ Wsl + bsl
    gemm_k<0><<<dim3(1, MH/64), 256>>>(xm, Wsl, bsl, nullptr, lg, 64, 64);
    // 4. temp + gumbel softmax -> g_sw
    router_softmax<<<MH/8, 256>>>(tw2, tb2, bias, gumbel);
    // 5. dispatch: st = sw^T @ xm (segmented) + snorm
    dispatch_partial<<<dim3(Bc*Hc, SEGc), 256>>>();
    dispatch_reduce<<<Bc*Hc, 256>>>();
    // 6. slice attention
    slice_attn<<<Bc*Hc, 256>>>(Wq, Wk, Wv);
    // 7. scatter back: y = sw @ out_st
    scatter_back<<<Bc*(Nc/32)*Hc, 256>>>();
    // 8. o2 = y @ Wp + bp + x
    gemm_k<1><<<dim3(Dc/64, Mrows/64), 256>>>(y, Wp, bp, x, o2, Dc, Dc);
    // 9. ln = layernorm(o2)
    ln_k<<<Mrows, 128>>>(ln2g, ln2b);
    // 10. mid = gelu(ln @ W1 + b1)
    gemm_k<2><<<dim3(HIDc/64, Mrows/64), 256>>>(ln, W1, b1, nullptr, mid, Dc, HIDc);
    // 11. out = mid @ W2 + b2 + x
    gemm_k<1><<<dim3(Dc/64, Mrows/64), 256>>>(mid, W2, b2, x, out, HIDc, Dc);
}

// round 2
// speedup vs baseline: 2.3052x; 2.3052x over previous
#include <cuda_runtime.h>
#include <math.h>

// Problem constants
#define Bc   4
#define Nc   8192
#define Dc   512
#define Hc   8
#define DHc  64
#define Kc   64
#define HIDc 1024
#define Mrows (Bc*Nc)        // 32768
#define MH    (Mrows*Hc)     // 262144 token-heads
#define SEGc  16
#define SEGLEN (Nc/SEGc)     // 512

// Scratch (device globals; no allocation allowed)
__device__ float g_xm   [(size_t)Mrows*Dc];
__device__ float g_t1   [(size_t)MH*Kc];
__device__ float g_logit[(size_t)MH*Kc];
__device__ float g_sw   [(size_t)MH*Kc];
__device__ float g_stp  [Bc*Hc*SEGc*Kc*DHc];
__device__ float g_snp  [Bc*Hc*SEGc*Kc];
__device__ float g_st   [Bc*Hc*Kc*DHc];
__device__ float g_ost  [Bc*Hc*Kc*DHc];
__device__ float g_y    [(size_t)Mrows*Dc];
__device__ float g_o2   [(size_t)Mrows*Dc];
__device__ float g_ln   [(size_t)Mrows*Dc];
__device__ float g_mid  [(size_t)Mrows*HIDc];

__device__ __forceinline__ float gelu_f(float x) {
    return 0.5f * x * (1.0f + erff(0.70710678118654752440f * x));
}

__device__ __forceinline__ unsigned f2tf32(float x) {
    unsigned r;
    asm("cvt.rna.tf32.f32 %0, %1;\n" : "=r"(r) : "f"(x));
    return r;
}

__device__ __forceinline__ void mma_tf32(float* c, const unsigned* a, const unsigned* b) {
    asm volatile(
        "mma.sync.aligned.m16n8k8.row.col.f32.tf32.tf32.f32 "
        "{%0,%1,%2,%3}, {%4,%5,%6,%7}, {%8,%9}, {%0,%1,%2,%3};\n"
        : "+f"(c[0]), "+f"(c[1]), "+f"(c[2]), "+f"(c[3])
        : "r"(a[0]), "r"(a[1]), "r"(a[2]), "r"(a[3]), "r"(b[0]), "r"(b[1]));
}

__device__ __forceinline__ void cpa16(void* s, const void* g) {
    unsigned sa = (unsigned)__cvta_generic_to_shared(s);
    asm volatile("cp.async.cg.shared.global [%0], [%1], 16;\n" :: "r"(sa), "l"(g));
}
#define CP_COMMIT() asm volatile("cp.async.commit_group;\n")
#define CP_WAIT1()  asm volatile("cp.async.wait_group 1;\n")
#define CP_WAIT0()  asm volatile("cp.async.wait_group 0;\n")

// ---------------------------------------------------------------------------
// TF32 tensor-core GEMM: C[M,Nd] = A[M,Kd] @ B[Kd,Nd] (+bias) epilogues.
// BM=128, BN=128, BK=16, 256 threads (8 warps, 2x4 warp grid, 64x32 warp tile)
// EPI: 0 = +bias, 1 = +bias+res, 2 = gelu(+bias)
// M%128==0, Kd%16==0, Nd%128==0 assumed.
// ---------------------------------------------------------------------------
#define BMt 128
#define BNt 128
#define BKt 16

template<int EPI>
__global__ __launch_bounds__(256, 2) void gemm_tf32(
    const float* __restrict__ A, const float* __restrict__ Bm,
    const float* __restrict__ bias, const float* __restrict__ res,
    float* __restrict__ C, int Kd, int Nd)
{
    __shared__ float As[2][BMt][BKt + 4];   // row stride 20 words -> conflict-free frags
    __shared__ float Bs[2][BKt][BNt + 8];   // row stride 136 words -> conflict-free frags

    const int t = threadIdx.x;
    const int warp = t >> 5, lane = t & 31;
    const int g = lane >> 2, q = lane & 3;
    const int wm = (warp >> 2) << 6;         // 0 / 64
    const int wn = (warp & 3) << 5;          // 0,32,64,96
    const int m0 = blockIdx.y * BMt;
    const int n0 = blockIdx.x * BNt;

    const int arow = t >> 2,  acol = (t & 3) << 2;
    const int brow = t >> 5,  bcol = (t & 31) << 2;
    const float* Ap = A + (size_t)(m0 + arow) * Kd + acol;
    const float* Bp = Bm + (size_t)brow * Nd + n0 + bcol;

    float acc[4][4][4] = {};

    // tile loader
    auto load_tile = [&](int buf, int k0) {
        cpa16(&As[buf][arow][acol],      Ap + k0);
        cpa16(&As[buf][arow + 64][acol], Ap + (size_t)64 * Kd + k0);
        cpa16(&Bs[buf][brow][bcol],      Bp + (size_t)k0 * Nd);
        cpa16(&Bs[buf][brow + 8][bcol],  Bp + (size_t)(k0 + 8) * Nd);
        CP_COMMIT();
    };

    const int nk = Kd / BKt;
    load_tile(0, 0);

    for (int it = 0; it < nk; ++it) {
        if (it + 1 < nk) { load_tile((it + 1) & 1, (it + 1) * BKt); CP_WAIT1(); }
        else             { CP_WAIT0(); }
        __syncthreads();
        const int buf = it & 1;
        #pragma unroll
        for (int ks = 0; ks < 2; ks++) {
            const int kb = ks * 8;
            unsigned af[4][4], bf[4][2];
            #pragma unroll
            for (int mt = 0; mt < 4; mt++) {
                int r = wm + mt * 16 + g;
                af[mt][0] = f2tf32(As[buf][r][kb + q]);
                af[mt][1] = f2tf32(As[buf][r + 8][kb + q]);
                af[mt][2] = f2tf32(As[buf][r][kb + q + 4]);
                af[mt][3] = f2tf32(As[buf][r + 8][kb + q + 4]);
            }
            #pragma unroll
            for (int nt = 0; nt < 4; nt++) {
                int c = wn + nt * 8 + g;
                bf[nt][0] = f2tf32(Bs[buf][kb + q][c]);
                bf[nt][1] = f2tf32(Bs[buf][kb + q + 4][c]);
            }
            #pragma unroll
            for (int mt = 0; mt < 4; mt++)
                #pragma unroll
                for (int nt = 0; nt < 4; nt++)
                    mma_tf32(acc[mt][nt], af[mt], bf[nt]);
        }
        __syncthreads();
    }

    // Epilogue
    #pragma unroll
    for (int nt = 0; nt < 4; nt++) {
        const int col = n0 + wn + nt * 8 + (q << 1);
        const float b0 = bias[col], b1 = bias[col + 1];
        #pragma unroll
        for (int mt = 0; mt < 4; mt++) {
            int r0 = m0 + wm + mt * 16 + g;
            int r1 = r0 + 8;
            float v0 = acc[mt][nt][0] + b0, v1 = acc[mt][nt][1] + b1;
            float v2 = acc[mt][nt][2] + b0, v3 = acc[mt][nt][3] + b1;
            if (EPI == 2) { v0 = gelu_f(v0); v1 = gelu_f(v1); v2 = gelu_f(v2); v3 = gelu_f(v3); }
            if (EPI == 1) {
                const float2 ra = *(const float2*)&res[(size_t)r0 * Nd + col];
                const float2 rb = *(const float2*)&res[(size_t)r1 * Nd + col];
                v0 += ra.x; v1 += ra.y; v2 += rb.x; v3 += rb.y;
            }
            *(float2*)&C[(size_t)r0 * Nd + col] = make_float2(v0, v1);
            *(float2*)&C[(size_t)r1 * Nd + col] = make_float2(v2, v3);
        }
    }
}

// ---------------------------------------------------------------------------
// Small FFMA GEMM (kept for N=64,K=64 router projections)
// ---------------------------------------------------------------------------
template<int EPI>
__global__ __launch_bounds__(256) void gemm_k(
    const float* __restrict__ A, const float* __restrict__ Bm,
    const float* __restrict__ bias, const float* __restrict__ res,
    float* __restrict__ C, int Kd, int Nd)
{
    __shared__ float As[16][68];
    __shared__ float Bs[16][64];
    const int t  = threadIdx.x;
    const int tx = t & 15, ty = t >> 4;
    const int m0 = blockIdx.y << 6;
    const int n0 = blockIdx.x << 6;
    const int ar = t >> 2,  ak = (t & 3) << 2;
    const int br = t >> 4,  bc = (t & 15) << 2;
    const float* Aptr = A + (size_t)(m0 + ar) * Kd + ak;
    const float* Bptr = Bm + (size_t)br * Nd + n0 + bc;

    float acc[4][4] = {};
    for (int k0 = 0; k0 < Kd; k0 += 16) {
        float4 av = *(const float4*)(Aptr + k0);
        float4 bv = *(const float4*)(Bptr + (size_t)k0 * Nd);
        As[ak+0][ar] = av.x; As[ak+1][ar] = av.y;
        As[ak+2][ar] = av.z; As[ak+3][ar] = av.w;
        *(float4*)&Bs[br][bc] = bv;
        __syncthreads();
        #pragma unroll
        for (int kk = 0; kk < 16; kk++) {
            float4 a4 = *(const float4*)&As[kk][ty << 2];
            float4 b4 = *(const float4*)&Bs[kk][tx << 2];
            acc[0][0] += a4.x*b4.x; acc[0][1] += a4.x*b4.y; acc[0][2] += a4.x*b4.z; acc[0][3] += a4.x*b4.w;
            acc[1][0] += a4.y*b4.x; acc[1][1] += a4.y*b4.y; acc[1][2] += a4.y*b4.z; acc[1][3] += a4.y*b4.w;
            acc[2][0] += a4.z*b4.x; acc[2][1] += a4.z*b4.y; acc[2][2] += a4.z*b4.z; acc[2][3] += a4.z*b4.w;
            acc[3][0] += a4.w*b4.x; acc[3][1] += a4.w*b4.y; acc[3][2] += a4.w*b4.z; acc[3][3] += a4.w*b4.w;
        }
        __syncthreads();
    }
    const int col = n0 + (tx << 2);
    float4 bb = *(const float4*)&bias[col];
    #pragma unroll
    for (int i = 0; i < 4; i++) {
        int row = m0 + (ty << 2) + i;
        float4 v;
        v.x = acc[i][0] + bb.x; v.y = acc[i][1] + bb.y;
        v.z = acc[i][2] + bb.z; v.w = acc[i][3] + bb.w;
        if (EPI == 2) {
            v.x = gelu_f(v.x); v.y = gelu_f(v.y); v.z = gelu_f(v.z); v.w = gelu_f(v.w);
        }
        if (EPI == 1) {
            float4 r = *(const float4*)&res[(size_t)row * Nd + col];
            v.x += r.x; v.y += r.y; v.z += r.z; v.w += r.w;
        }
        *(float4*)&C[(size_t)row * Nd + col] = v;
    }
}

// ---------------------------------------------------------------------------
__global__ __launch_bounds__(256) void router_softmax(
    const float* __restrict__ tw2, const float* __restrict__ tb2,
    const float* __restrict__ bias, const float* __restrict__ gumbel)
{
    int warp = (blockIdx.x << 3) + (threadIdx.x >> 5);
    int lane = threadIdx.x & 31;
    size_t base = (size_t)warp * 64;
    int h  = warp & 7;
    int bn = warp >> 3;
    int n  = bn & (Nc - 1);
    int b  = bn >> 13;

    float t1a = g_t1[base + lane], t1b = g_t1[base + lane + 32];
    float v = t1a * tw2[lane] + t1b * tw2[lane + 32];
    #pragma unroll
    for (int off = 16; off; off >>= 1) v += __shfl_xor_sync(0xffffffffu, v, off);
    float temp = fmaxf(gelu_f(v + tb2[0]) + bias[h], 0.01f);
    float invT = 1.0f / temp;

    size_t gbase = ((((size_t)b * Hc + h) * Nc + n)) * 64;
    float za = (g_logit[base + lane]      + gumbel[gbase + lane])      * invT;
    float zb = (g_logit[base + lane + 32] + gumbel[gbase + lane + 32]) * invT;
    float m = fmaxf(za, zb);
    #pragma unroll
    for (int off = 16; off; off >>= 1) m = fmaxf(m, __shfl_xor_sync(0xffffffffu, m, off));
    float ea = expf(za - m), eb = expf(zb - m);
    float s = ea + eb;
    #pragma unroll
    for (int off = 16; off; off >>= 1) s += __shfl_xor_sync(0xffffffffu, s, off);
    float inv = 1.0f / s;
    g_sw[base + lane]      = ea * inv;
    g_sw[base + lane + 32] = eb * inv;
}

// ---------------------------------------------------------------------------
__global__ __launch_bounds__(256) void dispatch_partial()
{
    int bh = blockIdx.x, s = blockIdx.y;
    int b = bh >> 3, h = bh & 7;
    int t = threadIdx.x;
    int tx = t & 15, ty = t >> 4;
    __shared__ float sws[32][64];
    __shared__ float xms[32][64];
    float acc[4][4] = {};
    float sn = 0.f;
    int nbase = s * SEGLEN;
    for (int ch = 0; ch < SEGLEN; ch += 32) {
        #pragma unroll
        for (int j = 0; j < 8; j++) {
            int idx = t + (j << 8);
            int r = idx >> 6, c = idx & 63;
            size_t nrow = (size_t)(b * Nc + nbase + ch + r);
            xms[r][c] = g_xm[nrow * Dc + h * 64 + c];
            sws[r][c] = g_sw[(nrow * Hc + h) * 64 + c];
        }
        __syncthreads();
        if (t < 64) {
            #pragma unroll
            for (int nn = 0; nn < 32; nn++) sn += sws[nn][t];
        }
        #pragma unroll 4
        for (int nn = 0; nn < 32; nn++) {
            float4 a4 = *(const float4*)&sws[nn][ty << 2];
            float4 b4 = *(const float4*)&xms[nn][tx << 2];
            acc[0][0] += a4.x*b4.x; acc[0][1] += a4.x*b4.y; acc[0][2] += a4.x*b4.z; acc[0][3] += a4.x*b4.w;
            acc[1][0] += a4.y*b4.x; acc[1][1] += a4.y*b4.y; acc[1][2] += a4.y*b4.z; acc[1][3] += a4.y*b4.w;
            acc[2][0] += a4.z*b4.x; acc[2][1] += a4.z*b4.y; acc[2][2] += a4.z*b4.z; acc[2][3] += a4.z*b4.w;
            acc[3][0] += a4.w*b4.x; acc[3][1] += a4.w*b4.y; acc[3][2] += a4.w*b4.z; acc[3][3] += a4.w*b4.w;
        }
        __syncthreads();
    }
    int base = (bh * SEGc + s) * 64;
    #pragma unroll
    for (int i = 0; i < 4; i++)
        #pragma unroll
        for (int j = 0; j < 4; j++)
            g_stp[(size_t)(base + (ty << 2) + i) * 64 + (tx << 2) + j] = acc[i][j];
    if (t < 64) g_snp[base + t] = sn;
}

__global__ __launch_bounds__(256) void dispatch_reduce()
{
    int bh = blockIdx.x, t = threadIdx.x;
    __shared__ float sn[64];
    if (t < 64) {
        float v = 1e-5f;
        for (int s = 0; s < SEGc; s++) v += g_snp[(bh * SEGc + s) * 64 + t];
        sn[t] = v;
    }
    __syncthreads();
    #pragma unroll
    for (int e = 0; e < 16; e++) {
        int idx = t + (e << 8);
        float v = 0.f;
        for (int s = 0; s < SEGc; s++) v += g_stp[(size_t)(bh * SEGc + s) * 4096 + idx];
        g_st[(size_t)bh * 4096 + idx] = v / sn[idx >> 6];
    }
}

// ---------------------------------------------------------------------------
__global__ __launch_bounds__(256) void slice_attn(
    const float* __restrict__ Wq, const float* __restrict__ Wk, const float* __restrict__ Wv)
{
    __shared__ float Ash[64][64];
    __shared__ float Ksh[64][64];
    __shared__ float Vsh[64][64];
    int bh = blockIdx.x, t = threadIdx.x;
    int i = t >> 2, c0 = (t & 3) << 4;

    #pragma unroll
    for (int e = 0; e < 16; e++) {
        int idx = t + (e << 8);
        Ash[idx >> 6][idx & 63] = g_st[(size_t)bh * 4096 + idx];
    }
    __syncthreads();

    float qr[16], kr[16], vr[16];
    #pragma unroll
    for (int e = 0; e < 16; e++) { qr[e] = 0.f; kr[e] = 0.f; vr[e] = 0.f; }
    for (int d = 0; d < 64; d++) {
        float sv = Ash[i][d];
        #pragma unroll
        for (int e = 0; e < 16; e++) {
            qr[e] += sv * Wq[d * 64 + c0 + e];
            kr[e] += sv * Wk[d * 64 + c0 + e];
            vr[e] += sv * Wv[d * 64 + c0 + e];
        }
    }
    __syncthreads();
    #pragma unroll
    for (int e = 0; e < 16; e++) { Ash[i][c0+e] = qr[e]; Ksh[i][c0+e] = kr[e]; Vsh[i][c0+e] = vr[e]; }
    __syncthreads();

    float sr[16];
    #pragma unroll
    for (int e = 0; e < 16; e++) {
        float sacc = 0.f;
        for (int d = 0; d < 64; d++) sacc += Ash[i][d] * Ksh[c0 + e][d];
        sr[e] = sacc * 0.125f;
    }
    __syncthreads();
    #pragma unroll
    for (int e = 0; e < 16; e++) Ash[i][c0 + e] = sr[e];
    __syncthreads();

    if (t < 64) {
        float mx = -1e30f;
        for (int j = 0; j < 64; j++) mx = fmaxf(mx, Ash[t][j]);
        float sum = 0.f;
        for (int j = 0; j < 64; j++) { float ee = expf(Ash[t][j] - mx); Ash[t][j] = ee; sum += ee; }
        float inv = 1.f / sum;
        for (int j = 0; j < 64; j++) Ash[t][j] *= inv;
    }
    __syncthreads();

    #pragma unroll
    for (int e = 0; e < 16; e++) {
        float o = 0.f;
        for (int j = 0; j < 64; j++) o += Ash[i][j] * Vsh[j][c0 + e];
        g_ost[(size_t)bh * 4096 + i * 64 + c0 + e] = o;
    }
}

// ---------------------------------------------------------------------------
__global__ __launch_bounds__(256) void scatter_back()
{
    int tile = blockIdx.x;
    int h  = tile & 7;
    int nt = (tile >> 3) & 255;
    int b  = tile >> 11;
    int bh = b * Hc + h;
    int t = threadIdx.x;
    __shared__ float osh[64][64];
    __shared__ float swsh[32][64];
    #pragma unroll
    for (int e = 0; e < 16; e++) {
        int idx = t + (e << 8);
        osh[idx >> 6][idx & 63] = g_ost[(size_t)bh * 4096 + idx];
    }
    #pragma unroll
    for (int e = 0; e < 8; e++) {
        int idx = t + (e << 8);
        int r = idx >> 6, c = idx & 63;
        swsh[r][c] = g_sw[(((size_t)(b * Nc + nt * 32 + r)) * Hc + h) * 64 + c];
    }
    __syncthreads();
    int tt = t >> 3, c0 = (t & 7) << 3;
    float o[8] = {};
    for (int g = 0; g < 64; g++) {
        float swv = swsh[tt][g];
        #pragma unroll
        for (int e = 0; e < 8; e++) o[e] += swv * osh[g][c0 + e];
    }
    int n = nt * 32 + tt;
    #pragma unroll
    for (int e = 0; e < 8; e++)
        g_y[((size_t)(b * Nc + n)) * Dc + h * 64 + c0 + e] = o[e];
}

// ---------------------------------------------------------------------------
__global__ __launch_bounds__(128) void ln_k(
    const float* __restrict__ gam, const float* __restrict__ bet)
{
    int row = blockIdx.x, t = threadIdx.x;
    const float4 v = *(const float4*)&g_o2[(size_t)row * Dc + (t << 2)];
    float s = v.x + v.y + v.z + v.w;
    __shared__ float rs[4];
    #pragma unroll
    for (int off = 16; off; off >>= 1) s += __shfl_xor_sync(0xffffffffu, s, off);
    int w = t >> 5;
    if ((t & 31) == 0) rs[w] = s;
    __syncthreads();
    float mean = (rs[0] + rs[1] + rs[2] + rs[3]) * (1.f / 512.f);
    float dx = v.x - mean, dy = v.y - mean, dz = v.z - mean, dw = v.w - mean;
    float q = dx*dx + dy*dy + dz*dz + dw*dw;
    #pragma unroll
    for (int off = 16; off; off >>= 1) q += __shfl_xor_sync(0xffffffffu, q, off);
    __syncthreads();
    if ((t & 31) == 0) rs[w] = q;
    __syncthreads();
    float var = (rs[0] + rs[1] + rs[2] + rs[3]) * (1.f / 512.f);
    float inv = rsqrtf(var + 1e-5f);
    float4 gv = *(const float4*)&gam[t << 2];
    float4 bv = *(const float4*)&bet[t << 2];
    float4 o;
    o.x = dx * inv * gv.x + bv.x;
    o.y = dy * inv * gv.y + bv.y;
    o.z = dz * inv * gv.z + bv.z;
    o.w = dw * inv * gv.w + bv.w;
    *(float4*)&g_ln[(size_t)row * Dc + (t << 2)] = o;
}

// ---------------------------------------------------------------------------
extern "C" void kernel_launch(void* const* d_in, const int* in_sizes, int n_in,
                              void* d_out, int out_size)
{
    const float* x      = (const float*)d_in[0];
    const float* gumbel = (const float*)d_in[1];
    const float* Wx     = (const float*)d_in[2];
    const float* bx     = (const float*)d_in[3];
    const float* tw1    = (const float*)d_in[4];
    const float* tb1    = (const float*)d_in[5];
    const float* tw2    = (const float*)d_in[6];
    const float* tb2    = (const float*)d_in[7];
    const float* bias   = (const float*)d_in[8];
    const float* Wsl    = (const float*)d_in[9];
    const float* bsl    = (const float*)d_in[10];
    const float* Wq     = (const float*)d_in[11];
    const float* Wk     = (const float*)d_in[12];
    const float* Wv     = (const float*)d_in[13];
    const float* Wp     = (const float*)d_in[14];
    const float* bp     = (const float*)d_in[15];
    const float* ln2g   = (const float*)d_in[16];
    const float* ln2b   = (const float*)d_in[17];
    const float* W1     = (const float*)d_in[18];
    const float* b1     = (const float*)d_in[19];
    const float* W2     = (const float*)d_in[20];
    const float* b2     = (const float*)d_in[21];
    float* out = (float*)d_out;

    float *xm, *t1, *lg, *y, *o2, *ln, *mid;
    cudaGetSymbolAddress((void**)&xm,  g_xm);
    cudaGetSymbolAddress((void**)&t1,  g_t1);
    cudaGetSymbolAddress((void**)&lg,  g_logit);
    cudaGetSymbolAddress((void**)&y,   g_y);
    cudaGetSymbolAddress((void**)&o2,  g_o2);
    cudaGetSymbolAddress((void**)&ln,  g_ln);
    cudaGetSymbolAddress((void**)&mid, g_mid);

    // 1. xm = x @ Wx + bx       (tensor cores)
    gemm_tf32<0><<<dim3(Dc/BNt, Mrows/BMt), 256>>>(x, Wx, bx, nullptr, xm, Dc, Dc);
    // 2. t1 = gelu(xm @ tw1 + tb1)   (small FFMA)
    gemm_k<2><<<dim3(1, MH/64), 256>>>(xm, tw1, tb1, nullptr, t1, 64, 64);
    // 3. logits = xm @ Wsl + bsl
    gemm_k<0><<<dim3(1, MH/64), 256>>>(xm, Wsl, bsl, nullptr, lg, 64, 64);
    // 4. temp + gumbel softmax -> g_sw
    router_softmax<<<MH/8, 256>>>(tw2, tb2, bias, gumbel);
    // 5. dispatch
    dispatch_partial<<<dim3(Bc*Hc, SEGc), 256>>>();
    dispatch_reduce<<<Bc*Hc, 256>>>();
    // 6. slice attention
    slice_attn<<<Bc*Hc, 256>>>(Wq, Wk, Wv);
    // 7. scatter back
    scatter_back<<<Bc*(Nc/32)*Hc, 256>>>();
    // 8. o2 = y @ Wp + bp + x   (tensor cores)
    gemm_tf32<1><<<dim3(Dc/BNt, Mrows/BMt), 256>>>(y, Wp, bp, x, o2, Dc, Dc);
    // 9. layernorm
    ln_k<<<Mrows, 128>>>(ln2g, ln2b);
    // 10. mid = gelu(ln @ W1 + b1)
    gemm_tf32<2><<<dim3(HIDc/BNt, Mrows/BMt), 256>>>(ln, W1, b1, nullptr, mid, Dc, HIDc);
    // 11. out = mid @ W2 + b2 + x
    gemm_tf32<1><<<dim3(Dc/BNt, Mrows/BMt), 256>>>(mid, W2, b2, x, out, HIDc, Dc);
}

// round 3
// speedup vs baseline: 2.4239x; 1.0515x over previous
#include <cuda_runtime.h>
#include <math.h>

// Problem constants
#define Bc   4
#define Nc   8192
#define Dc   512
#define Hc   8
#define DHc  64
#define Kc   64
#define HIDc 1024
#define Mrows (Bc*Nc)        // 32768
#define MH    (Mrows*Hc)     // 262144 token-heads
#define SEGc  16
#define SEGLEN (Nc/SEGc)     // 512

// Scratch (device globals; no allocation allowed)
__device__ float g_xm   [(size_t)Mrows*Dc];
__device__ float g_sw   [(size_t)MH*Kc];
__device__ float g_stp  [Bc*Hc*SEGc*Kc*DHc];
__device__ float g_snp  [Bc*Hc*SEGc*Kc];
__device__ float g_ost  [Bc*Hc*Kc*DHc];
__device__ float g_y    [(size_t)Mrows*Dc];
__device__ float g_o2   [(size_t)Mrows*Dc];
__device__ float g_ln   [(size_t)Mrows*Dc];
__device__ float g_mid  [(size_t)Mrows*HIDc];

__device__ __forceinline__ float gelu_f(float x) {
    return 0.5f * x * (1.0f + erff(0.70710678118654752440f * x));
}

__device__ __forceinline__ unsigned f2tf32(float x) {
    unsigned r;
    asm("cvt.rna.tf32.f32 %0, %1;\n" : "=r"(r) : "f"(x));
    return r;
}

__device__ __forceinline__ void mma_tf32(float* c, const unsigned* a, const unsigned* b) {
    asm volatile(
        "mma.sync.aligned.m16n8k8.row.col.f32.tf32.tf32.f32 "
        "{%0,%1,%2,%3}, {%4,%5,%6,%7}, {%8,%9}, {%0,%1,%2,%3};\n"
        : "+f"(c[0]), "+f"(c[1]), "+f"(c[2]), "+f"(c[3])
        : "r"(a[0]), "r"(a[1]), "r"(a[2]), "r"(a[3]), "r"(b[0]), "r"(b[1]));
}

__device__ __forceinline__ void cpa16(void* s, const void* g) {
    unsigned sa = (unsigned)__cvta_generic_to_shared(s);
    asm volatile("cp.async.cg.shared.global [%0], [%1], 16;\n" :: "r"(sa), "l"(g));
}
#define CP_COMMIT() asm volatile("cp.async.commit_group;\n")
#define CP_WAIT2()  asm volatile("cp.async.wait_group 2;\n")
#define CP_WAIT1()  asm volatile("cp.async.wait_group 1;\n")
#define CP_WAIT0()  asm volatile("cp.async.wait_group 0;\n")

// ---------------------------------------------------------------------------
// TF32 tensor-core GEMM, 3-stage cp.async pipeline.
// BM=128, BN=128, BK=16, 256 threads (8 warps, 2x4 grid, 64x32 warp tile)
// EPI: 0 = +bias, 1 = +bias+res, 2 = gelu(+bias)
// ---------------------------------------------------------------------------
#define BMt 128
#define BNt 128
#define BKt 16
#define NST 3
#define ASTRIDE 20
#define BSTRIDE 136
#define GEMM_SMEM (NST*(BMt*ASTRIDE + BKt*BSTRIDE)*4)

template<int EPI>
__global__ __launch_bounds__(256, 2) void gemm_tf32(
    const float* __restrict__ A, const float* __restrict__ Bm,
    const float* __restrict__ bias, const float* __restrict__ res,
    float* __restrict__ C, int Kd, int Nd)
{
    extern __shared__ float sm[];
    float* Asm = sm;                                // [NST][BMt][ASTRIDE]
    float* Bsm = sm + NST * BMt * ASTRIDE;          // [NST][BKt][BSTRIDE]

    const int t = threadIdx.x;
    const int warp = t >> 5, lane = t & 31;
    const int g = lane >> 2, q = lane & 3;
    const int wm = (warp >> 2) << 6;
    const int wn = (warp & 3) << 5;
    const int m0 = blockIdx.y * BMt;
    const int n0 = blockIdx.x * BNt;

    const int arow = t >> 2,  acol = (t & 3) << 2;
    const int brow = t >> 5,  bcol = (t & 31) << 2;
    const float* Ap = A + (size_t)(m0 + arow) * Kd + acol;
    const float* Bp = Bm + (size_t)brow * Nd + n0 + bcol;

    float acc[4][4][4] = {};

    auto load_tile = [&](int buf, int k0) {
        float* As = Asm + buf * BMt * ASTRIDE;
        float* Bs = Bsm + buf * BKt * BSTRIDE;
        cpa16(As + arow * ASTRIDE + acol,        Ap + k0);
        cpa16(As + (arow + 64) * ASTRIDE + acol, Ap + (size_t)64 * Kd + k0);
        cpa16(Bs + brow * BSTRIDE + bcol,        Bp + (size_t)k0 * Nd);
        cpa16(Bs + (brow + 8) * BSTRIDE + bcol,  Bp + (size_t)(k0 + 8) * Nd);
        CP_COMMIT();
    };

    const int nk = Kd / BKt;    // >= 32
    load_tile(0, 0);
    load_tile(1, BKt);

    for (int it = 0; it < nk; ++it) {
        if (it + 2 < nk)       { load_tile((it + 2) % NST, (it + 2) * BKt); CP_WAIT2(); }
        else if (it + 2 == nk) { CP_WAIT1(); }
        else                   { CP_WAIT0(); }
        __syncthreads();
        const int buf = it % NST;
        const float* As = Asm + buf * BMt * ASTRIDE;
        const float* Bs = Bsm + buf * BKt * BSTRIDE;
        #pragma unroll
        for (int ks = 0; ks < 2; ks++) {
            const int kb = ks * 8;
            unsigned af[4][4], bf[4][2];
            #pragma unroll
            for (int mt = 0; mt < 4; mt++) {
                int r = wm + mt * 16 + g;
                af[mt][0] = f2tf32(As[r * ASTRIDE + kb + q]);
                af[mt][1] = f2tf32(As[(r + 8) * ASTRIDE + kb + q]);
                af[mt][2] = f2tf32(As[r * ASTRIDE + kb + q + 4]);
                af[mt][3] = f2tf32(As[(r + 8) * ASTRIDE + kb + q + 4]);
            }
            #pragma unroll
            for (int nt = 0; nt < 4; nt++) {
                int c = wn + nt * 8 + g;
                bf[nt][0] = f2tf32(Bs[(kb + q) * BSTRIDE + c]);
                bf[nt][1] = f2tf32(Bs[(kb + q + 4) * BSTRIDE + c]);
            }
            #pragma unroll
            for (int mt = 0; mt < 4; mt++)
                #pragma unroll
                for (int nt = 0; nt < 4; nt++)
                    mma_tf32(acc[mt][nt], af[mt], bf[nt]);
        }
        __syncthreads();
    }

    #pragma unroll
    for (int nt = 0; nt < 4; nt++) {
        const int col = n0 + wn + nt * 8 + (q << 1);
        const float b0 = bias[col], b1 = bias[col + 1];
        #pragma unroll
        for (int mt = 0; mt < 4; mt++) {
            int r0 = m0 + wm + mt * 16 + g;
            int r1 = r0 + 8;
            float v0 = acc[mt][nt][0] + b0, v1 = acc[mt][nt][1] + b1;
            float v2 = acc[mt][nt][2] + b0, v3 = acc[mt][nt][3] + b1;
            if (EPI == 2) { v0 = gelu_f(v0); v1 = gelu_f(v1); v2 = gelu_f(v2); v3 = gelu_f(v3); }
            if (EPI == 1) {
                const float2 ra = *(const float2*)&res[(size_t)r0 * Nd + col];
                const float2 rb = *(const float2*)&res[(size_t)r1 * Nd + col];
                v0 += ra.x; v1 += ra.y; v2 += rb.x; v3 += rb.y;
            }
            *(float2*)&C[(size_t)r0 * Nd + col] = make_float2(v0, v1);
            *(float2*)&C[(size_t)r1 * Nd + col] = make_float2(v2, v3);
        }
    }
}

// ---------------------------------------------------------------------------
// Fused router: for each token-head row m (xm viewed as [MH,64]):
//   t1 = gelu(xm@tw1+tb1); temp = max(gelu(t1@tw2+tb2)+bias[h], .01)
//   sw = softmax((xm@Wsl+bsl+gumbel)/temp)       -> g_sw
// Block: 64 rows, 256 threads (16x16), all in registers + smem weights.
// ---------------------------------------------------------------------------
__global__ __launch_bounds__(256) void fused_router(
    const float* __restrict__ tw1, const float* __restrict__ tb1,
    const float* __restrict__ tw2, const float* __restrict__ tb2,
    const float* __restrict__ bias, const float* __restrict__ Wsl,
    const float* __restrict__ bsl, const float* __restrict__ gumbel)
{
    __shared__ float As[64][64];    // xm tile transposed [k][m]
    __shared__ float W1s[64][64];   // tw1 [d][k]
    __shared__ float W2s[64][64];   // Wsl [d][k]
    const int t = threadIdx.x;
    const int tx = t & 15, ty = t >> 4;
    const int m0 = blockIdx.x << 6;
    const int c0 = tx << 2;

    {   // load xm tile (transposed) and weights
        const int ar = t >> 2, ak = (t & 3) << 2;
        float4 av = *(const float4*)&g_xm[(size_t)(m0 + ar) * 64 + ak];
        As[ak + 0][ar] = av.x; As[ak + 1][ar] = av.y;
        As[ak + 2][ar] = av.z; As[ak + 3][ar] = av.w;
        #pragma unroll
        for (int p = 0; p < 4; p++) {
            int r = (t >> 4) + p * 16, c = (t & 15) << 2;
            *(float4*)&W1s[r][c] = *(const float4*)&tw1[r * 64 + c];
            *(float4*)&W2s[r][c] = *(const float4*)&Wsl[r * 64 + c];
        }
    }
    __syncthreads();

    float acc1[4][4] = {}, acc2[4][4] = {};
    #pragma unroll 8
    for (int kk = 0; kk < 64; kk++) {
        float4 a4 = *(const float4*)&As[kk][ty << 2];
        float4 w1 = *(const float4*)&W1s[kk][c0];
        float4 w2 = *(const float4*)&W2s[kk][c0];
        const float a[4] = {a4.x, a4.y, a4.z, a4.w};
        const float u[4] = {w1.x, w1.y, w1.z, w1.w};
        const float v[4] = {w2.x, w2.y, w2.z, w2.w};
        #pragma unroll
        for (int i = 0; i < 4; i++)
            #pragma unroll
            for (int j = 0; j < 4; j++) {
                acc1[i][j] += a[i] * u[j];
                acc2[i][j] += a[i] * v[j];
            }
    }

    // temperature: p_i = sum_j gelu(acc1+tb1)*tw2, half-warp reduce
    const float4 tb = *(const float4*)&tb1[c0];
    const float4 t2 = *(const float4*)&tw2[c0];
    const float4 bs = *(const float4*)&bsl[c0];
    const float tbv[4] = {tb.x, tb.y, tb.z, tb.w};
    const float t2v[4] = {t2.x, t2.y, t2.z, t2.w};
    const float bsv[4] = {bs.x, bs.y, bs.z, bs.w};
    const float tb2v = tb2[0];

    #pragma unroll
    for (int i = 0; i < 4; i++) {
        const int m = m0 + (ty << 2) + i;
        float p = 0.f;
        #pragma unroll
        for (int j = 0; j < 4; j++) p += gelu_f(acc1[i][j] + tbv[j]) * t2v[j];
        #pragma unroll
        for (int off = 8; off; off >>= 1) p += __shfl_xor_sync(0xffffffffu, p, off, 16);
        const float invT = 1.0f / fmaxf(gelu_f(p + tb2v) + bias[m & 7], 0.01f);

        // logits for this row: z = (acc2 + bsl + gumbel) * invT
        const size_t gidx = (((size_t)(m >> 16) * Hc + (m & 7)) * Nc + ((m >> 3) & (Nc - 1))) * 64 + c0;
        const float4 gu = *(const float4*)&gumbel[gidx];
        float z[4];
        z[0] = (acc2[i][0] + bsv[0] + gu.x) * invT;
        z[1] = (acc2[i][1] + bsv[1] + gu.y) * invT;
        z[2] = (acc2[i][2] + bsv[2] + gu.z) * invT;
        z[3] = (acc2[i][3] + bsv[3] + gu.w) * invT;

        float mx = fmaxf(fmaxf(z[0], z[1]), fmaxf(z[2], z[3]));
        #pragma unroll
        for (int off = 8; off; off >>= 1) mx = fmaxf(mx, __shfl_xor_sync(0xffffffffu, mx, off, 16));
        float e0 = expf(z[0] - mx), e1 = expf(z[1] - mx), e2 = expf(z[2] - mx), e3 = expf(z[3] - mx);
        float s = e0 + e1 + e2 + e3;
        #pragma unroll
        for (int off = 8; off; off >>= 1) s += __shfl_xor_sync(0xffffffffu, s, off, 16);
        const float inv = 1.0f / s;
        *(float4*)&g_sw[(size_t)m * 64 + c0] = make_float4(e0 * inv, e1 * inv, e2 * inv, e3 * inv);
    }
}

// ---------------------------------------------------------------------------
__global__ __launch_bounds__(256) void dispatch_partial()
{
    int bh = blockIdx.x, s = blockIdx.y;
    int b = bh >> 3, h = bh & 7;
    int t = threadIdx.x;
    int tx = t & 15, ty = t >> 4;
    __shared__ float sws[32][64];
    __shared__ float xms[32][64];
    float acc[4][4] = {};
    float sn = 0.f;
    int nbase = s * SEGLEN;
    for (int ch = 0; ch < SEGLEN; ch += 32) {
        #pragma unroll
        for (int j = 0; j < 8; j++) {
            int idx = t + (j << 8);
            int r = idx >> 6, c = idx & 63;
            size_t nrow = (size_t)(b * Nc + nbase + ch + r);
            xms[r][c] = g_xm[nrow * Dc + h * 64 + c];
            sws[r][c] = g_sw[(nrow * Hc + h) * 64 + c];
        }
        __syncthreads();
        if (t < 64) {
            #pragma unroll
            for (int nn = 0; nn < 32; nn++) sn += sws[nn][t];
        }
        #pragma unroll 4
        for (int nn = 0; nn < 32; nn++) {
            float4 a4 = *(const float4*)&sws[nn][ty << 2];
            float4 b4 = *(const float4*)&xms[nn][tx << 2];
            acc[0][0] += a4.x*b4.x; acc[0][1] += a4.x*b4.y; acc[0][2] += a4.x*b4.z; acc[0][3] += a4.x*b4.w;
            acc[1][0] += a4.y*b4.x; acc[1][1] += a4.y*b4.y; acc[1][2] += a4.y*b4.z; acc[1][3] += a4.y*b4.w;
            acc[2][0] += a4.z*b4.x; acc[2][1] += a4.z*b4.y; acc[2][2] += a4.z*b4.z; acc[2][3] += a4.z*b4.w;
            acc[3][0] += a4.w*b4.x; acc[3][1] += a4.w*b4.y; acc[3][2] += a4.w*b4.z; acc[3][3] += a4.w*b4.w;
        }
        __syncthreads();
    }
    int base = (bh * SEGc + s) * 64;
    #pragma unroll
    for (int i = 0; i < 4; i++)
        #pragma unroll
        for (int j = 0; j < 4; j++)
            g_stp[(size_t)(base + (ty << 2) + i) * 64 + (tx << 2) + j] = acc[i][j];
    if (t < 64) g_snp[base + t] = sn;
}

// ---------------------------------------------------------------------------
// Fused reduce + slice attention per (b,h).
// ---------------------------------------------------------------------------
__global__ __launch_bounds__(256) void slice_attn(
    const float* __restrict__ Wq, const float* __restrict__ Wk, const float* __restrict__ Wv)
{
    __shared__ float Ash[64][64];
    __shared__ float Ksh[64][64];
    __shared__ float Vsh[64][64];
    __shared__ float snh[64];
    int bh = blockIdx.x, t = threadIdx.x;
    int i = t >> 2, c0 = (t & 3) << 4;

    if (t < 64) {
        float v = 1e-5f;
        for (int s = 0; s < SEGc; s++) v += g_snp[(bh * SEGc + s) * 64 + t];
        snh[t] = 1.0f / v;
    }
    __syncthreads();
    #pragma unroll
    for (int e = 0; e < 16; e++) {
        int idx = t + (e << 8);
        float v = 0.f;
        for (int s = 0; s < SEGc; s++) v += g_stp[(size_t)(bh * SEGc + s) * 4096 + idx];
        Ash[idx >> 6][idx & 63] = v * snh[idx >> 6];
    }
    __syncthreads();

    float qr[16], kr[16], vr[16];
    #pragma unroll
    for (int e = 0; e < 16; e++) { qr[e] = 0.f; kr[e] = 0.f; vr[e] = 0.f; }
    for (int d = 0; d < 64; d++) {
        float sv = Ash[i][d];
        #pragma unroll
        for (int e = 0; e < 16; e++) {
            qr[e] += sv * Wq[d * 64 + c0 + e];
            kr[e] += sv * Wk[d * 64 + c0 + e];
            vr[e] += sv * Wv[d * 64 + c0 + e];
        }
    }
    __syncthreads();
    #pragma unroll
    for (int e = 0; e < 16; e++) { Ash[i][c0+e] = qr[e]; Ksh[i][c0+e] = kr[e]; Vsh[i][c0+e] = vr[e]; }
    __syncthreads();

    float sr[16];
    #pragma unroll
    for (int e = 0; e < 16; e++) {
        float sacc = 0.f;
        for (int d = 0; d < 64; d++) sacc += Ash[i][d] * Ksh[c0 + e][d];
        sr[e] = sacc * 0.125f;
    }
    __syncthreads();
    #pragma unroll
    for (int e = 0; e < 16; e++) Ash[i][c0 + e] = sr[e];
    __syncthreads();

    if (t < 64) {
        float mx = -1e30f;
        for (int j = 0; j < 64; j++) mx = fmaxf(mx, Ash[t][j]);
        float sum = 0.f;
        for (int j = 0; j < 64; j++) { float ee = expf(Ash[t][j] - mx); Ash[t][j] = ee; sum += ee; }
        float inv = 1.f / sum;
        for (int j = 0; j < 64; j++) Ash[t][j] *= inv;
    }
    __syncthreads();

    #pragma unroll
    for (int e = 0; e < 16; e++) {
        float o = 0.f;
        for (int j = 0; j < 64; j++) o += Ash[i][j] * Vsh[j][c0 + e];
        g_ost[(size_t)bh * 4096 + i * 64 + c0 + e] = o;
    }
}

// ---------------------------------------------------------------------------
__global__ __launch_bounds__(256) void scatter_back()
{
    int tile = blockIdx.x;
    int h  = tile & 7;
    int nt = (tile >> 3) & 255;
    int b  = tile >> 11;
    int bh = b * Hc + h;
    int t = threadIdx.x;
    __shared__ float osh[64][64];
    __shared__ float swsh[32][64];
    #pragma unroll
    for (int e = 0; e < 16; e++) {
        int idx = t + (e << 8);
        osh[idx >> 6][idx & 63] = g_ost[(size_t)bh * 4096 + idx];
    }
    #pragma unroll
    for (int e = 0; e < 8; e++) {
        int idx = t + (e << 8);
        int r = idx >> 6, c = idx & 63;
        swsh[r][c] = g_sw[(((size_t)(b * Nc + nt * 32 + r)) * Hc + h) * 64 + c];
    }
    __syncthreads();
    int tt = t >> 3, c0 = (t & 7) << 3;
    float o[8] = {};
    for (int g = 0; g < 64; g++) {
        float swv = swsh[tt][g];
        #pragma unroll
        for (int e = 0; e < 8; e++) o[e] += swv * osh[g][c0 + e];
    }
    int n = nt * 32 + tt;
    #pragma unroll
    for (int e = 0; e < 8; e++)
        g_y[((size_t)(b * Nc + n)) * Dc + h * 64 + c0 + e] = o[e];
}

// ---------------------------------------------------------------------------
__global__ __launch_bounds__(128) void ln_k(
    const float* __restrict__ gam, const float* __restrict__ bet)
{
    int row = blockIdx.x, t = threadIdx.x;
    const float4 v = *(const float4*)&g_o2[(size_t)row * Dc + (t << 2)];
    float s = v.x + v.y + v.z + v.w;
    __shared__ float rs[4];
    #pragma unroll
    for (int off = 16; off; off >>= 1) s += __shfl_xor_sync(0xffffffffu, s, off);
    int w = t >> 5;
    if ((t & 31) == 0) rs[w] = s;
    __syncthreads();
    float mean = (rs[0] + rs[1] + rs[2] + rs[3]) * (1.f / 512.f);
    float dx = v.x - mean, dy = v.y - mean, dz = v.z - mean, dw = v.w - mean;
    float q = dx*dx + dy*dy + dz*dz + dw*dw;
    #pragma unroll
    for (int off = 16; off; off >>= 1) q += __shfl_xor_sync(0xffffffffu, q, off);
    __syncthreads();
    if ((t & 31) == 0) rs[w] = q;
    __syncthreads();
    float var = (rs[0] + rs[1] + rs[2] + rs[3]) * (1.f / 512.f);
    float inv = rsqrtf(var + 1e-5f);
    float4 gv = *(const float4*)&gam[t << 2];
    float4 bv = *(const float4*)&bet[t << 2];
    float4 o;
    o.x = dx * inv * gv.x + bv.x;
    o.y = dy * inv * gv.y + bv.y;
    o.z = dz * inv * gv.z + bv.z;
    o.w = dw * inv * gv.w + bv.w;
    *(float4*)&g_ln[(size_t)row * Dc + (t << 2)] = o;
}

// ---------------------------------------------------------------------------
extern "C" void kernel_launch(void* const* d_in, const int* in_sizes, int n_in,
                              void* d_out, int out_size)
{
    const float* x      = (const float*)d_in[0];
    const float* gumbel = (const float*)d_in[1];
    const float* Wx     = (const float*)d_in[2];
    const float* bx     = (const float*)d_in[3];
    const float* tw1    = (const float*)d_in[4];
    const float* tb1    = (const float*)d_in[5];
    const float* tw2    = (const float*)d_in[6];
    const float* tb2    = (const float*)d_in[7];
    const float* bias   = (const float*)d_in[8];
    const float* Wsl    = (const float*)d_in[9];
    const float* bsl    = (const float*)d_in[10];
    const float* Wq     = (const float*)d_in[11];
    const float* Wk     = (const float*)d_in[12];
    const float* Wv     = (const float*)d_in[13];
    const float* Wp     = (const float*)d_in[14];
    const float* bp     = (const float*)d_in[15];
    const float* ln2g   = (const float*)d_in[16];
    const float* ln2b   = (const float*)d_in[17];
    const float* W1     = (const float*)d_in[18];
    const float* b1     = (const float*)d_in[19];
    const float* W2     = (const float*)d_in[20];
    const float* b2     = (const float*)d_in[21];
    float* out = (float*)d_out;

    float *xm, *y, *o2, *ln, *mid;
    cudaGetSymbolAddress((void**)&xm,  g_xm);
    cudaGetSymbolAddress((void**)&y,   g_y);
    cudaGetSymbolAddress((void**)&o2,  g_o2);
    cudaGetSymbolAddress((void**)&ln,  g_ln);
    cudaGetSymbolAddress((void**)&mid, g_mid);

    cudaFuncSetAttribute(gemm_tf32<0>, cudaFuncAttributeMaxDynamicSharedMemorySize, GEMM_SMEM);
    cudaFuncSetAttribute(gemm_tf32<1>, cudaFuncAttributeMaxDynamicSharedMemorySize, GEMM_SMEM);
    cudaFuncSetAttribute(gemm_tf32<2>, cudaFuncAttributeMaxDynamicSharedMemorySize, GEMM_SMEM);

    // 1. xm = x @ Wx + bx
    gemm_tf32<0><<<dim3(Dc/BNt, Mrows/BMt), 256, GEMM_SMEM>>>(x, Wx, bx, nullptr, xm, Dc, Dc);
    // 2. fused router -> g_sw
    fused_router<<<MH/64, 256>>>(tw1, tb1, tw2, tb2, bias, Wsl, bsl, gumbel);
    // 3. dispatch
    dispatch_partial<<<dim3(Bc*Hc, SEGc), 256>>>();
    // 4. reduce + slice attention
    slice_attn<<<Bc*Hc, 256>>>(Wq, Wk, Wv);
    // 5. scatter back
    scatter_back<<<Bc*(Nc/32)*Hc, 256>>>();
    // 6. o2 = y @ Wp + bp + x
    gemm_tf32<1><<<dim3(Dc/BNt, Mrows/BMt), 256, GEMM_SMEM>>>(y, Wp, bp, x, o2, Dc, Dc);
    // 7. layernorm
    ln_k<<<Mrows, 128>>>(ln2g, ln2b);
    // 8. mid = gelu(ln @ W1 + b1)
    gemm_tf32<2><<<dim3(HIDc/BNt, Mrows/BMt), 256, GEMM_SMEM>>>(ln, W1, b1, nullptr, mid, Dc, HIDc);
    // 9. out = mid @ W2 + b2 + x
    gemm_tf32<1><<<dim3(Dc/BNt, Mrows/BMt), 256, GEMM_SMEM>>>(mid, W2, b2, x, out, HIDc, Dc);
}

// round 4
// speedup vs baseline: 2.5633x; 1.0575x over previous
#include <cuda_runtime.h>
#include <math.h>

// Problem constants
#define Bc   4
#define Nc   8192
#define Dc   512
#define Hc   8
#define DHc  64
#define Kc   64
#define HIDc 1024
#define Mrows (Bc*Nc)        // 32768
#define MH    (Mrows*Hc)     // 262144 token-heads
#define SEGc  16
#define SEGLEN (Nc/SEGc)     // 512

// Scratch (device globals; no allocation allowed)
__device__ float g_xm   [(size_t)Mrows*Dc];
__device__ float g_sw   [(size_t)MH*Kc];
__device__ float g_stp  [Bc*Hc*SEGc*Kc*DHc];
__device__ float g_snp  [Bc*Hc*SEGc*Kc];
__device__ float g_ost  [Bc*Hc*Kc*DHc];
__device__ float g_y    [(size_t)Mrows*Dc];
__device__ float g_o2   [(size_t)Mrows*Dc];
__device__ float g_ln   [(size_t)Mrows*Dc];
__device__ float g_mid  [(size_t)Mrows*HIDc];

__device__ __forceinline__ float gelu_f(float x) {
    return 0.5f * x * (1.0f + erff(0.70710678118654752440f * x));
}

__device__ __forceinline__ void mma_tf32(float* c, const unsigned* a, const unsigned* b) {
    asm volatile(
        "mma.sync.aligned.m16n8k8.row.col.f32.tf32.tf32.f32 "
        "{%0,%1,%2,%3}, {%4,%5,%6,%7}, {%8,%9}, {%0,%1,%2,%3};\n"
        : "+f"(c[0]), "+f"(c[1]), "+f"(c[2]), "+f"(c[3])
        : "r"(a[0]), "r"(a[1]), "r"(a[2]), "r"(a[3]), "r"(b[0]), "r"(b[1]));
}

__device__ __forceinline__ void ldsm4(unsigned* r, const float* p) {
    unsigned a = (unsigned)__cvta_generic_to_shared(p);
    asm volatile("ldmatrix.sync.aligned.m8n8.x4.shared.b16 {%0,%1,%2,%3}, [%4];\n"
        : "=r"(r[0]), "=r"(r[1]), "=r"(r[2]), "=r"(r[3]) : "r"(a));
}

__device__ __forceinline__ void cpa16(void* s, const void* g) {
    unsigned sa = (unsigned)__cvta_generic_to_shared(s);
    asm volatile("cp.async.cg.shared.global [%0], [%1], 16;\n" :: "r"(sa), "l"(g));
}
#define CP_COMMIT() asm volatile("cp.async.commit_group;\n")
#define CP_WAIT2()  asm volatile("cp.async.wait_group 2;\n")
#define CP_WAIT1()  asm volatile("cp.async.wait_group 1;\n")
#define CP_WAIT0()  asm volatile("cp.async.wait_group 0;\n")

// ---------------------------------------------------------------------------
// TF32 tensor-core GEMM, 3-stage cp.async pipeline, ldmatrix A-fragments.
// BM=128, BN=128, BK=16, 256 threads (8 warps, 2x4 grid, 64x32 warp tile)
// EPI: 0 = +bias, 1 = +bias+res, 2 = gelu(+bias)
// ---------------------------------------------------------------------------
#define BMt 128
#define BNt 128
#define BKt 16
#define NST 3
#define ASTRIDE 20
#define BSTRIDE 136
#define GEMM_SMEM (NST*(BMt*ASTRIDE + BKt*BSTRIDE)*4)

template<int EPI>
__global__ __launch_bounds__(256, 2) void gemm_tf32(
    const float* __restrict__ A, const float* __restrict__ Bm,
    const float* __restrict__ bias, const float* __restrict__ res,
    float* __restrict__ C, int Kd, int Nd)
{
    extern __shared__ float sm[];
    float* Asm = sm;                                // [NST][BMt][ASTRIDE]
    float* Bsm = sm + NST * BMt * ASTRIDE;          // [NST][BKt][BSTRIDE]

    const int t = threadIdx.x;
    const int warp = t >> 5, lane = t & 31;
    const int g = lane >> 2, q = lane & 3;
    const int wm = (warp >> 2) << 6;
    const int wn = (warp & 3) << 5;
    const int m0 = blockIdx.y * BMt;
    const int n0 = blockIdx.x * BNt;

    // ldmatrix source row/k-offset for this lane (per A fragment)
    const int lrow = lane & 15;
    const int lkof = (lane & 16) >> 2;   // 0 or 4

    const int arow = t >> 2,  acol = (t & 3) << 2;
    const int brow = t >> 5,  bcol = (t & 31) << 2;
    const float* Ap = A + (size_t)(m0 + arow) * Kd + acol;
    const float* Bp = Bm + (size_t)brow * Nd + n0 + bcol;

    float acc[4][4][4] = {};

    auto load_tile = [&](int buf, int k0) {
        float* As = Asm + buf * BMt * ASTRIDE;
        float* Bs = Bsm + buf * BKt * BSTRIDE;
        cpa16(As + arow * ASTRIDE + acol,        Ap + k0);
        cpa16(As + (arow + 64) * ASTRIDE + acol, Ap + (size_t)64 * Kd + k0);
        cpa16(Bs + brow * BSTRIDE + bcol,        Bp + (size_t)k0 * Nd);
        cpa16(Bs + (brow + 8) * BSTRIDE + bcol,  Bp + (size_t)(k0 + 8) * Nd);
        CP_COMMIT();
    };

    const int nk = Kd / BKt;
    load_tile(0, 0);
    load_tile(1, BKt);

    for (int it = 0; it < nk; ++it) {
        if (it + 2 < nk)       { load_tile((it + 2) % NST, (it + 2) * BKt); CP_WAIT2(); }
        else if (it + 2 == nk) { CP_WAIT1(); }
        else                   { CP_WAIT0(); }
        __syncthreads();
        const int buf = it % NST;
        const float* As = Asm + buf * BMt * ASTRIDE;
        const float* Bs = Bsm + buf * BKt * BSTRIDE;
        #pragma unroll
        for (int ks = 0; ks < 2; ks++) {
            const int kb = ks * 8;
            unsigned af[4][4], bf[4][2];
            #pragma unroll
            for (int mt = 0; mt < 4; mt++)
                ldsm4(af[mt], As + (wm + mt * 16 + lrow) * ASTRIDE + kb + lkof);
            #pragma unroll
            for (int nt = 0; nt < 4; nt++) {
                int c = wn + nt * 8 + g;
                bf[nt][0] = __float_as_uint(Bs[(kb + q) * BSTRIDE + c]);
                bf[nt][1] = __float_as_uint(Bs[(kb + q + 4) * BSTRIDE + c]);
            }
            #pragma unroll
            for (int mt = 0; mt < 4; mt++)
                #pragma unroll
                for (int nt = 0; nt < 4; nt++)
                    mma_tf32(acc[mt][nt], af[mt], bf[nt]);
        }
        __syncthreads();
    }

    #pragma unroll
    for (int nt = 0; nt < 4; nt++) {
        const int col = n0 + wn + nt * 8 + (q << 1);
        const float b0 = bias[col], b1 = bias[col + 1];
        #pragma unroll
        for (int mt = 0; mt < 4; mt++) {
            int r0 = m0 + wm + mt * 16 + g;
            int r1 = r0 + 8;
            float v0 = acc[mt][nt][0] + b0, v1 = acc[mt][nt][1] + b1;
            float v2 = acc[mt][nt][2] + b0, v3 = acc[mt][nt][3] + b1;
            if (EPI == 2) { v0 = gelu_f(v0); v1 = gelu_f(v1); v2 = gelu_f(v2); v3 = gelu_f(v3); }
            if (EPI == 1) {
                const float2 ra = *(const float2*)&res[(size_t)r0 * Nd + col];
                const float2 rb = *(const float2*)&res[(size_t)r1 * Nd + col];
                v0 += ra.x; v1 += ra.y; v2 += rb.x; v3 += rb.y;
            }
            *(float2*)&C[(size_t)r0 * Nd + col] = make_float2(v0, v1);
            *(float2*)&C[(size_t)r1 * Nd + col] = make_float2(v2, v3);
        }
    }
}

// ---------------------------------------------------------------------------
// Fused router (unchanged from R3)
// ---------------------------------------------------------------------------
__global__ __launch_bounds__(256) void fused_router(
    const float* __restrict__ tw1, const float* __restrict__ tb1,
    const float* __restrict__ tw2, const float* __restrict__ tb2,
    const float* __restrict__ bias, const float* __restrict__ Wsl,
    const float* __restrict__ bsl, const float* __restrict__ gumbel)
{
    __shared__ float As[64][64];
    __shared__ float W1s[64][64];
    __shared__ float W2s[64][64];
    const int t = threadIdx.x;
    const int tx = t & 15, ty = t >> 4;
    const int m0 = blockIdx.x << 6;
    const int c0 = tx << 2;

    {
        const int ar = t >> 2, ak = (t & 3) << 2;
        float4 av = *(const float4*)&g_xm[(size_t)(m0 + ar) * 64 + ak];
        As[ak + 0][ar] = av.x; As[ak + 1][ar] = av.y;
        As[ak + 2][ar] = av.z; As[ak + 3][ar] = av.w;
        #pragma unroll
        for (int p = 0; p < 4; p++) {
            int r = (t >> 4) + p * 16, c = (t & 15) << 2;
            *(float4*)&W1s[r][c] = *(const float4*)&tw1[r * 64 + c];
            *(float4*)&W2s[r][c] = *(const float4*)&Wsl[r * 64 + c];
        }
    }
    __syncthreads();

    float acc1[4][4] = {}, acc2[4][4] = {};
    #pragma unroll 8
    for (int kk = 0; kk < 64; kk++) {
        float4 a4 = *(const float4*)&As[kk][ty << 2];
        float4 w1 = *(const float4*)&W1s[kk][c0];
        float4 w2 = *(const float4*)&W2s[kk][c0];
        const float a[4] = {a4.x, a4.y, a4.z, a4.w};
        const float u[4] = {w1.x, w1.y, w1.z, w1.w};
        const float v[4] = {w2.x, w2.y, w2.z, w2.w};
        #pragma unroll
        for (int i = 0; i < 4; i++)
            #pragma unroll
            for (int j = 0; j < 4; j++) {
                acc1[i][j] += a[i] * u[j];
                acc2[i][j] += a[i] * v[j];
            }
    }

    const float4 tb = *(const float4*)&tb1[c0];
    const float4 t2 = *(const float4*)&tw2[c0];
    const float4 bs = *(const float4*)&bsl[c0];
    const float tbv[4] = {tb.x, tb.y, tb.z, tb.w};
    const float t2v[4] = {t2.x, t2.y, t2.z, t2.w};
    const float bsv[4] = {bs.x, bs.y, bs.z, bs.w};
    const float tb2v = tb2[0];

    #pragma unroll
    for (int i = 0; i < 4; i++) {
        const int m = m0 + (ty << 2) + i;
        float p = 0.f;
        #pragma unroll
        for (int j = 0; j < 4; j++) p += gelu_f(acc1[i][j] + tbv[j]) * t2v[j];
        #pragma unroll
        for (int off = 8; off; off >>= 1) p += __shfl_xor_sync(0xffffffffu, p, off, 16);
        const float invT = 1.0f / fmaxf(gelu_f(p + tb2v) + bias[m & 7], 0.01f);

        const size_t gidx = (((size_t)(m >> 16) * Hc + (m & 7)) * Nc + ((m >> 3) & (Nc - 1))) * 64 + c0;
        const float4 gu = *(const float4*)&gumbel[gidx];
        float z[4];
        z[0] = (acc2[i][0] + bsv[0] + gu.x) * invT;
        z[1] = (acc2[i][1] + bsv[1] + gu.y) * invT;
        z[2] = (acc2[i][2] + bsv[2] + gu.z) * invT;
        z[3] = (acc2[i][3] + bsv[3] + gu.w) * invT;

        float mx = fmaxf(fmaxf(z[0], z[1]), fmaxf(z[2], z[3]));
        #pragma unroll
        for (int off = 8; off; off >>= 1) mx = fmaxf(mx, __shfl_xor_sync(0xffffffffu, mx, off, 16));
        float e0 = expf(z[0] - mx), e1 = expf(z[1] - mx), e2 = expf(z[2] - mx), e3 = expf(z[3] - mx);
        float s = e0 + e1 + e2 + e3;
        #pragma unroll
        for (int off = 8; off; off >>= 1) s += __shfl_xor_sync(0xffffffffu, s, off, 16);
        const float inv = 1.0f / s;
        *(float4*)&g_sw[(size_t)m * 64 + c0] = make_float4(e0 * inv, e1 * inv, e2 * inv, e3 * inv);
    }
}

// ---------------------------------------------------------------------------
__global__ __launch_bounds__(256) void dispatch_partial()
{
    int bh = blockIdx.x, s = blockIdx.y;
    int b = bh >> 3, h = bh & 7;
    int t = threadIdx.x;
    int tx = t & 15, ty = t >> 4;
    __shared__ float sws[32][64];
    __shared__ float xms[32][64];
    float acc[4][4] = {};
    float sn = 0.f;
    int nbase = s * SEGLEN;
    for (int ch = 0; ch < SEGLEN; ch += 32) {
        #pragma unroll
        for (int j = 0; j < 8; j++) {
            int idx = t + (j << 8);
            int r = idx >> 6, c = idx & 63;
            size_t nrow = (size_t)(b * Nc + nbase + ch + r);
            xms[r][c] = g_xm[nrow * Dc + h * 64 + c];
            sws[r][c] = g_sw[(nrow * Hc + h) * 64 + c];
        }
        __syncthreads();
        if (t < 64) {
            #pragma unroll
            for (int nn = 0; nn < 32; nn++) sn += sws[nn][t];
        }
        #pragma unroll 4
        for (int nn = 0; nn < 32; nn++) {
            float4 a4 = *(const float4*)&sws[nn][ty << 2];
            float4 b4 = *(const float4*)&xms[nn][tx << 2];
            acc[0][0] += a4.x*b4.x; acc[0][1] += a4.x*b4.y; acc[0][2] += a4.x*b4.z; acc[0][3] += a4.x*b4.w;
            acc[1][0] += a4.y*b4.x; acc[1][1] += a4.y*b4.y; acc[1][2] += a4.y*b4.z; acc[1][3] += a4.y*b4.w;
            acc[2][0] += a4.z*b4.x; acc[2][1] += a4.z*b4.y; acc[2][2] += a4.z*b4.z; acc[2][3] += a4.z*b4.w;
            acc[3][0] += a4.w*b4.x; acc[3][1] += a4.w*b4.y; acc[3][2] += a4.w*b4.z; acc[3][3] += a4.w*b4.w;
        }
        __syncthreads();
    }
    int base = (bh * SEGc + s) * 64;
    #pragma unroll
    for (int i = 0; i < 4; i++)
        #pragma unroll
        for (int j = 0; j < 4; j++)
            g_stp[(size_t)(base + (ty << 2) + i) * 64 + (tx << 2) + j] = acc[i][j];
    if (t < 64) g_snp[base + t] = sn;
}

// ---------------------------------------------------------------------------
// Fused reduce + slice attention, all operands staged in shared memory.
// Dynamic smem layout (floats, stride 68 rows):
//   STt[64][68]  (st transposed: [d][tok])
//   Wsm[3][64][68]
//   Qt[64][68] Kt[64][68] (transposed: [d][tok])  Vs[64][68] ([tok][d])
//   Pt[64][68]  (scores transposed: [j][i])
// ---------------------------------------------------------------------------
#define SA_R 68
#define SA_SMEM ((1+3+3+1)*64*SA_R*4)

__global__ __launch_bounds__(256) void slice_attn(
    const float* __restrict__ Wq, const float* __restrict__ Wk, const float* __restrict__ Wv)
{
    extern __shared__ float sm[];
    float* STt = sm;
    float* Wsm = STt + 64 * SA_R;
    float* Qt  = Wsm + 3 * 64 * SA_R;
    float* Kt  = Qt + 64 * SA_R;
    float* Vs  = Kt + 64 * SA_R;
    float* Pt  = Vs + 64 * SA_R;
    __shared__ float invsn[64];

    const int bh = blockIdx.x, t = threadIdx.x;
    const int tx = t & 15, ty = t >> 4;
    const int r4 = ty << 2, c4 = tx << 2;

    // snorm
    if (t < 64) {
        float v = 1e-5f;
        for (int s = 0; s < SEGc; s++) v += g_snp[(bh * SEGc + s) * 64 + t];
        invsn[t] = 1.0f / v;
    }
    // load W into smem
    const float* Wg[3] = {Wq, Wk, Wv};
    #pragma unroll
    for (int m = 0; m < 3; m++)
        #pragma unroll
        for (int e = 0; e < 4; e++) {
            int idx = (t + (e << 8)) << 2;   // 4096 elements as float4
            int r = idx >> 6, c = idx & 63;
            float4 w = *(const float4*)&Wg[m][idx];
            *(float4*)&Wsm[(m * 64 + r) * SA_R + c] = w;
        }
    __syncthreads();

    // reduce partials -> STt (transposed, normalized)
    #pragma unroll
    for (int e = 0; e < 16; e++) {
        int idx = t + (e << 8);
        float v = 0.f;
        #pragma unroll
        for (int s = 0; s < SEGc; s++) v += g_stp[(size_t)(bh * SEGc + s) * 4096 + idx];
        int tok = idx >> 6, d = idx & 63;
        STt[d * SA_R + tok] = v * invsn[tok];
    }
    __syncthreads();

    // QKV: C[tok][c] = sum_d st[tok][d] * W[d][c], 4x4 microtile
    {
        float aq[4][4] = {}, ak[4][4] = {}, av[4][4] = {};
        #pragma unroll 4
        for (int d = 0; d < 64; d++) {
            float4 a4 = *(const float4*)&STt[d * SA_R + r4];
            float4 wq4 = *(const float4*)&Wsm[(0 * 64 + d) * SA_R + c4];
            float4 wk4 = *(const float4*)&Wsm[(1 * 64 + d) * SA_R + c4];
            float4 wv4 = *(const float4*)&Wsm[(2 * 64 + d) * SA_R + c4];
            const float a[4] = {a4.x, a4.y, a4.z, a4.w};
            const float uq[4] = {wq4.x, wq4.y, wq4.z, wq4.w};
            const float uk[4] = {wk4.x, wk4.y, wk4.z, wk4.w};
            const float uv[4] = {wv4.x, wv4.y, wv4.z, wv4.w};
            #pragma unroll
            for (int i = 0; i < 4; i++)
                #pragma unroll
                for (int j = 0; j < 4; j++) {
                    aq[i][j] += a[i] * uq[j];
                    ak[i][j] += a[i] * uk[j];
                    av[i][j] += a[i] * uv[j];
                }
        }
        __syncthreads();
        #pragma unroll
        for (int i = 0; i < 4; i++)
            #pragma unroll
            for (int j = 0; j < 4; j++) {
                Qt[(c4 + j) * SA_R + r4 + i] = aq[i][j];   // transposed [c][tok]
                Kt[(c4 + j) * SA_R + r4 + i] = ak[i][j];
                Vs[(r4 + i) * SA_R + c4 + j] = av[i][j];   // natural [tok][c]
            }
    }
    __syncthreads();

    // scores: S[i][j] = (Q[i] . K[j]) / 8, store transposed Pt[j][i]
    {
        float sc[4][4] = {};
        #pragma unroll 4
        for (int d = 0; d < 64; d++) {
            float4 a4 = *(const float4*)&Qt[d * SA_R + r4];
            float4 b4 = *(const float4*)&Kt[d * SA_R + c4];
            const float a[4] = {a4.x, a4.y, a4.z, a4.w};
            const float b[4] = {b4.x, b4.y, b4.z, b4.w};
            #pragma unroll
            for (int i = 0; i < 4; i++)
                #pragma unroll
                for (int j = 0; j < 4; j++) sc[i][j] += a[i] * b[j];
        }
        __syncthreads();
        #pragma unroll
        for (int i = 0; i < 4; i++)
            #pragma unroll
            for (int j = 0; j < 4; j++)
                Pt[(c4 + j) * SA_R + r4 + i] = sc[i][j] * 0.125f;
    }
    __syncthreads();

    // softmax over j for each query row i (thread t = i)
    if (t < 64) {
        float mx = -1e30f;
        #pragma unroll 8
        for (int j = 0; j < 64; j++) mx = fmaxf(mx, Pt[j * SA_R + t]);
        float sum = 0.f;
        #pragma unroll 8
        for (int j = 0; j < 64; j++) {
            float ee = expf(Pt[j * SA_R + t] - mx);
            Pt[j * SA_R + t] = ee;
            sum += ee;
        }
        float inv = 1.f / sum;
        #pragma unroll 8
        for (int j = 0; j < 64; j++) Pt[j * SA_R + t] *= inv;
    }
    __syncthreads();

    // out = P @ V
    {
        float oc[4][4] = {};
        #pragma unroll 4
        for (int j = 0; j < 64; j++) {
            float4 a4 = *(const float4*)&Pt[j * SA_R + r4];
            float4 b4 = *(const float4*)&Vs[j * SA_R + c4];
            const float a[4] = {a4.x, a4.y, a4.z, a4.w};
            const float b[4] = {b4.x, b4.y, b4.z, b4.w};
            #pragma unroll
            for (int i = 0; i < 4; i++)
                #pragma unroll
                for (int jj = 0; jj < 4; jj++) oc[i][jj] += a[i] * b[jj];
        }
        #pragma unroll
        for (int i = 0; i < 4; i++)
            #pragma unroll
            for (int j = 0; j < 4; j++)
                g_ost[(size_t)bh * 4096 + (r4 + i) * 64 + c4 + j] = oc[i][j];
    }
}

// ---------------------------------------------------------------------------
__global__ __launch_bounds__(256) void scatter_back()
{
    int tile = blockIdx.x;
    int h  = tile & 7;
    int nt = (tile >> 3) & 255;
    int b  = tile >> 11;
    int bh = b * Hc + h;
    int t = threadIdx.x;
    __shared__ float osh[64][64];
    __shared__ float swsh[32][64];
    #pragma unroll
    for (int e = 0; e < 16; e++) {
        int idx = t + (e << 8);
        osh[idx >> 6][idx & 63] = g_ost[(size_t)bh * 4096 + idx];
    }
    #pragma unroll
    for (int e = 0; e < 8; e++) {
        int idx = t + (e << 8);
        int r = idx >> 6, c = idx & 63;
        swsh[r][c] = g_sw[(((size_t)(b * Nc + nt * 32 + r)) * Hc + h) * 64 + c];
    }
    __syncthreads();
    int tt = t >> 3, c0 = (t & 7) << 3;
    float o[8] = {};
    for (int g = 0; g < 64; g++) {
        float swv = swsh[tt][g];
        #pragma unroll
        for (int e = 0; e < 8; e++) o[e] += swv * osh[g][c0 + e];
    }
    int n = nt * 32 + tt;
    #pragma unroll
    for (int e = 0; e < 8; e++)
        g_y[((size_t)(b * Nc + n)) * Dc + h * 64 + c0 + e] = o[e];
}

// ---------------------------------------------------------------------------
__global__ __launch_bounds__(128) void ln_k(
    const float* __restrict__ gam, const float* __restrict__ bet)
{
    int row = blockIdx.x, t = threadIdx.x;
    const float4 v = *(const float4*)&g_o2[(size_t)row * Dc + (t << 2)];
    float s = v.x + v.y + v.z + v.w;
    __shared__ float rs[4];
    #pragma unroll
    for (int off = 16; off; off >>= 1) s += __shfl_xor_sync(0xffffffffu, s, off);
    int w = t >> 5;
    if ((t & 31) == 0) rs[w] = s;
    __syncthreads();
    float mean = (rs[0] + rs[1] + rs[2] + rs[3]) * (1.f / 512.f);
    float dx = v.x - mean, dy = v.y - mean, dz = v.z - mean, dw = v.w - mean;
    float q = dx*dx + dy*dy + dz*dz + dw*dw;
    #pragma unroll
    for (int off = 16; off; off >>= 1) q += __shfl_xor_sync(0xffffffffu, q, off);
    __syncthreads();
    if ((t & 31) == 0) rs[w] = q;
    __syncthreads();
    float var = (rs[0] + rs[1] + rs[2] + rs[3]) * (1.f / 512.f);
    float inv = rsqrtf(var + 1e-5f);
    float4 gv = *(const float4*)&gam[t << 2];
    float4 bv = *(const float4*)&bet[t << 2];
    float4 o;
    o.x = dx * inv * gv.x + bv.x;
    o.y = dy * inv * gv.y + bv.y;
    o.z = dz * inv * gv.z + bv.z;
    o.w = dw * inv * gv.w + bv.w;
    *(float4*)&g_ln[(size_t)row * Dc + (t << 2)] = o;
}

// ---------------------------------------------------------------------------
extern "C" void kernel_launch(void* const* d_in, const int* in_sizes, int n_in,
                              void* d_out, int out_size)
{
    const float* x      = (const float*)d_in[0];
    const float* gumbel = (const float*)d_in[1];
    const float* Wx     = (const float*)d_in[2];
    const float* bx     = (const float*)d_in[3];
    const float* tw1    = (const float*)d_in[4];
    const float* tb1    = (const float*)d_in[5];
    const float* tw2    = (const float*)d_in[6];
    const float* tb2    = (const float*)d_in[7];
    const float* bias   = (const float*)d_in[8];
    const float* Wsl    = (const float*)d_in[9];
    const float* bsl    = (const float*)d_in[10];
    const float* Wq     = (const float*)d_in[11];
    const float* Wk     = (const float*)d_in[12];
    const float* Wv     = (const float*)d_in[13];
    const float* Wp     = (const float*)d_in[14];
    const float* bp     = (const float*)d_in[15];
    const float* ln2g   = (const float*)d_in[16];
    const float* ln2b   = (const float*)d_in[17];
    const float* W1     = (const float*)d_in[18];
    const float* b1     = (const float*)d_in[19];
    const float* W2     = (const float*)d_in[20];
    const float* b2     = (const float*)d_in[21];
    float* out = (float*)d_out;

    float *xm, *y, *o2, *ln, *mid;
    cudaGetSymbolAddress((void**)&xm,  g_xm);
    cudaGetSymbolAddress((void**)&y,   g_y);
    cudaGetSymbolAddress((void**)&o2,  g_o2);
    cudaGetSymbolAddress((void**)&ln,  g_ln);
    cudaGetSymbolAddress((void**)&mid, g_mid);

    cudaFuncSetAttribute(gemm_tf32<0>, cudaFuncAttributeMaxDynamicSharedMemorySize, GEMM_SMEM);
    cudaFuncSetAttribute(gemm_tf32<1>, cudaFuncAttributeMaxDynamicSharedMemorySize, GEMM_SMEM);
    cudaFuncSetAttribute(gemm_tf32<2>, cudaFuncAttributeMaxDynamicSharedMemorySize, GEMM_SMEM);
    cudaFuncSetAttribute(slice_attn,   cudaFuncAttributeMaxDynamicSharedMemorySize, SA_SMEM);

    // 1. xm = x @ Wx + bx
    gemm_tf32<0><<<dim3(Dc/BNt, Mrows/BMt), 256, GEMM_SMEM>>>(x, Wx, bx, nullptr, xm, Dc, Dc);
    // 2. fused router -> g_sw
    fused_router<<<MH/64, 256>>>(tw1, tb1, tw2, tb2, bias, Wsl, bsl, gumbel);
    // 3. dispatch
    dispatch_partial<<<dim3(Bc*Hc, SEGc), 256>>>();
    // 4. reduce + slice attention
    slice_attn<<<Bc*Hc, 256, SA_SMEM>>>(Wq, Wk, Wv);
    // 5. scatter back
    scatter_back<<<Bc*(Nc/32)*Hc, 256>>>();
    // 6. o2 = y @ Wp + bp + x
    gemm_tf32<1><<<dim3(Dc/BNt, Mrows/BMt), 256, GEMM_SMEM>>>(y, Wp, bp, x, o2, Dc, Dc);
    // 7. layernorm
    ln_k<<<Mrows, 128>>>(ln2g, ln2b);
    // 8. mid = gelu(ln @ W1 + b1)
    gemm_tf32<2><<<dim3(HIDc/BNt, Mrows/BMt), 256, GEMM_SMEM>>>(ln, W1, b1, nullptr, mid, Dc, HIDc);
    // 9. out = mid @ W2 + b2 + x
    gemm_tf32<1><<<dim3(Dc/BNt, Mrows/BMt), 256, GEMM_SMEM>>>(mid, W2, b2, x, out, HIDc, Dc);
}

// round 6
// speedup vs baseline: 3.1677x; 1.2358x over previous
#include <cuda_runtime.h>
#include <cuda_fp16.h>
#include <math.h>
#include <stdint.h>

// Problem constants
#define Bc   4
#define Nc   8192
#define Dc   512
#define Hc   8
#define DHc  64
#define Kc   64
#define HIDc 1024
#define Mrows (Bc*Nc)        // 32768
#define MH    (Mrows*Hc)     // 262144 token-heads
#define SEGc  16
#define SEGLEN (Nc/SEGc)     // 512

// Scratch (device globals; no allocation allowed)
__device__ float  g_xm  [(size_t)Mrows*Dc];     // fp32 (router/dispatch consume)
__device__ float  g_sw  [(size_t)MH*Kc];
__device__ float  g_stp [Bc*Hc*SEGc*Kc*DHc];
__device__ float  g_snp [Bc*Hc*SEGc*Kc];
__device__ float  g_ost [Bc*Hc*Kc*DHc];
__device__ float  g_o2  [(size_t)Mrows*Dc];
// fp16 GEMM operands
__device__ __half g_xh  [(size_t)Mrows*Dc];     // x as fp16
__device__ __half g_yh  [(size_t)Mrows*Dc];     // scatter output
__device__ __half g_lnh [(size_t)Mrows*Dc];     // layernorm output
__device__ __half g_midh[(size_t)Mrows*HIDc];   // MLP mid
// transposed fp16 weights [N][K]
#define BT_WX 0
#define BT_WP 262144
#define BT_W1 524288
#define BT_W2 1048576
__device__ __half g_bth [1572864];

__device__ __forceinline__ float gelu_f(float x) {
    return 0.5f * x * (1.0f + erff(0.70710678118654752440f * x));
}

__device__ __forceinline__ unsigned s2u(const void* p) {
    return (unsigned)__cvta_generic_to_shared(p);
}
__device__ __forceinline__ void cpa16(void* s, const void* g) {
    unsigned sa = s2u(s);
    asm volatile("cp.async.cg.shared.global [%0], [%1], 16;\n" :: "r"(sa), "l"(g));
}
#define CP_COMMIT() asm volatile("cp.async.commit_group;\n")
#define CP_WAIT2()  asm volatile("cp.async.wait_group 2;\n")
#define CP_WAIT1()  asm volatile("cp.async.wait_group 1;\n")
#define CP_WAIT0()  asm volatile("cp.async.wait_group 0;\n")

__device__ __forceinline__ void mma_f16(float* c, const unsigned* a, const unsigned* b) {
    asm volatile(
        "mma.sync.aligned.m16n8k16.row.col.f32.f16.f16.f32 "
        "{%0,%1,%2,%3}, {%4,%5,%6,%7}, {%8,%9}, {%0,%1,%2,%3};\n"
        : "+f"(c[0]), "+f"(c[1]), "+f"(c[2]), "+f"(c[3])
        : "r"(a[0]), "r"(a[1]), "r"(a[2]), "r"(a[3]), "r"(b[0]), "r"(b[1]));
}
__device__ __forceinline__ void ldsm4(unsigned* r, const __half* p) {
    unsigned a = s2u(p);
    asm volatile("ldmatrix.sync.aligned.m8n8.x4.shared.b16 {%0,%1,%2,%3}, [%4];\n"
        : "=r"(r[0]), "=r"(r[1]), "=r"(r[2]), "=r"(r[3]) : "r"(a));
}

__device__ __forceinline__ void store2(float* C, size_t idx, float v0, float v1) {
    *(float2*)&C[idx] = make_float2(v0, v1);
}
__device__ __forceinline__ void store2(__half* C, size_t idx, float v0, float v1) {
    *(__half2*)&C[idx] = __floats2half2_rn(v0, v1);
}

// ---------------------------------------------------------------------------
// FP16 tensor-core GEMM: C[M,Nd] = A[M,Kd](h) @ Bt[Nd,Kd](h)^T (+bias) epi.
// BM=128, BN=128, BK=32, 256 threads (8 warps, 2x4 grid, 64x32 warp tile)
// EPI: 0 = +bias, 1 = +bias+res, 2 = gelu(+bias)
// ---------------------------------------------------------------------------
#define BKh 32
#define HS  40                       // smem row stride in halves (32 + 8 pad)
#define STAGEH (128*HS)              // halves per matrix per stage
#define NSTh 3
#define GEMM_SMEM (NSTh*2*STAGEH*2)  // bytes

template<int EPI, typename OutT>
__global__ __launch_bounds__(256, 2) void gemm_h16(
    const __half* __restrict__ A, const __half* __restrict__ Bt,
    const float* __restrict__ bias, const float* __restrict__ res,
    OutT* __restrict__ C, int Kd, int Nd)
{
    extern __shared__ __half smh[];

    const int t = threadIdx.x;
    const int warp = t >> 5, lane = t & 31;
    const int g = lane >> 2, q = lane & 3;
    const int wm = (warp >> 2) << 6;         // 0 / 64
    const int wn = (warp & 3) << 5;          // 0,32,64,96
    const int m0 = blockIdx.y << 7;
    const int n0 = blockIdx.x << 7;

    const int lrow = lane & 15;              // ldmatrix lane row
    const int lkof = (lane >> 4) << 3;       // ldmatrix lane col offset (halves)

    const int r128 = t >> 1;                 // loader row 0..127
    const int hoff = (t & 1) << 4;           // loader half-offset 0/16
    const __half* Ap = A  + (size_t)(m0 + r128) * Kd + hoff;
    const __half* Bp = Bt + (size_t)(n0 + r128) * Kd + hoff;

    float acc[4][4][4] = {};

    auto load_tile = [&](int buf, int k0) {
        __half* As = smh + buf * 2 * STAGEH;
        __half* Bs = As + STAGEH;
        cpa16(As + r128 * HS + hoff,     Ap + k0);
        cpa16(As + r128 * HS + hoff + 8, Ap + k0 + 8);
        cpa16(Bs + r128 * HS + hoff,     Bp + k0);
        cpa16(Bs + r128 * HS + hoff + 8, Bp + k0 + 8);
        CP_COMMIT();
    };

    const int nk = Kd / BKh;
    load_tile(0, 0);
    load_tile(1, BKh);

    for (int it = 0; it < nk; ++it) {
        if (it + 2 < nk)       { load_tile((it + 2) % NSTh, (it + 2) * BKh); CP_WAIT2(); }
        else if (it + 2 == nk) { CP_WAIT1(); }
        else                   { CP_WAIT0(); }
        __syncthreads();
        const __half* As = smh + (it % NSTh) * 2 * STAGEH;
        const __half* Bs = As + STAGEH;
        #pragma unroll
        for (int ks = 0; ks < 2; ks++) {
            const int kb = ks << 4;
            unsigned af[4][4], bf[4][2];
            #pragma unroll
            for (int mt = 0; mt < 4; mt++)
                ldsm4(af[mt], As + (wm + mt * 16 + lrow) * HS + kb + lkof);
            #pragma unroll
            for (int nt = 0; nt < 4; nt++) {
                const __half* bp = Bs + (wn + nt * 8 + g) * HS + kb + (q << 1);
                bf[nt][0] = *(const unsigned*)bp;
                bf[nt][1] = *(const unsigned*)(bp + 8);
            }
            #pragma unroll
            for (int mt = 0; mt < 4; mt++)
                #pragma unroll
                for (int nt = 0; nt < 4; nt++)
                    mma_f16(acc[mt][nt], af[mt], bf[nt]);
        }
        __syncthreads();
    }

    #pragma unroll
    for (int nt = 0; nt < 4; nt++) {
        const int col = n0 + wn + nt * 8 + (q << 1);
        const float b0 = bias[col], b1 = bias[col + 1];
        #pragma unroll
        for (int mt = 0; mt < 4; mt++) {
            int r0 = m0 + wm + mt * 16 + g;
            int r1 = r0 + 8;
            float v0 = acc[mt][nt][0] + b0, v1 = acc[mt][nt][1] + b1;
            float v2 = acc[mt][nt][2] + b0, v3 = acc[mt][nt][3] + b1;
            if (EPI == 2) { v0 = gelu_f(v0); v1 = gelu_f(v1); v2 = gelu_f(v2); v3 = gelu_f(v3); }
            if (EPI == 1) {
                const float2 ra = *(const float2*)&res[(size_t)r0 * Nd + col];
                const float2 rb = *(const float2*)&res[(size_t)r1 * Nd + col];
                v0 += ra.x; v1 += ra.y; v2 += rb.x; v3 += rb.y;
            }
            store2(C, (size_t)r0 * Nd + col, v0, v1);
            store2(C, (size_t)r1 * Nd + col, v2, v3);
        }
    }
}

// ---------------------------------------------------------------------------
// x (fp32) -> fp16 copy
// ---------------------------------------------------------------------------
__global__ __launch_bounds__(256) void convert_f2h(
    const float* __restrict__ S, __half* __restrict__ D)
{
    size_t i = ((size_t)blockIdx.x * 256 + threadIdx.x) * 8;
    float4 a = *(const float4*)&S[i];
    float4 b = *(const float4*)&S[i + 4];
    *(__half2*)&D[i]     = __floats2half2_rn(a.x, a.y);
    *(__half2*)&D[i + 2] = __floats2half2_rn(a.z, a.w);
    *(__half2*)&D[i + 4] = __floats2half2_rn(b.x, b.y);
    *(__half2*)&D[i + 6] = __floats2half2_rn(b.z, b.w);
}

// ---------------------------------------------------------------------------
// Weight transpose (fp32 -> fp16): D[c][r] = S[r][c]
// ---------------------------------------------------------------------------
__global__ __launch_bounds__(256) void transpose_k(
    const float* __restrict__ S, __half* __restrict__ D, int R, int Ccol)
{
    __shared__ float tl[32][33];
    int c0 = blockIdx.x << 5, r0 = blockIdx.y << 5;
    int x = threadIdx.x, y = threadIdx.y;
    #pragma unroll
    for (int j = 0; j < 32; j += 8)
        tl[y + j][x] = S[(size_t)(r0 + y + j) * Ccol + c0 + x];
    __syncthreads();
    #pragma unroll
    for (int j = 0; j < 32; j += 8)
        D[(size_t)(c0 + y + j) * R + r0 + x] = __float2half_rn(tl[x][y + j]);
}

// ---------------------------------------------------------------------------
// Fused router (unchanged)
// ---------------------------------------------------------------------------
__global__ __launch_bounds__(256) void fused_router(
    const float* __restrict__ tw1, const float* __restrict__ tb1,
    const float* __restrict__ tw2, const float* __restrict__ tb2,
    const float* __restrict__ bias, const float* __restrict__ Wsl,
    const float* __restrict__ bsl, const float* __restrict__ gumbel)
{
    __shared__ float As[64][64];
    __shared__ float W1s[64][64];
    __shared__ float W2s[64][64];
    const int t = threadIdx.x;
    const int tx = t & 15, ty = t >> 4;
    const int m0 = blockIdx.x << 6;
    const int c0 = tx << 2;

    {
        const int ar = t >> 2, ak = (t & 3) << 2;
        float4 av = *(const float4*)&g_xm[(size_t)(m0 + ar) * 64 + ak];
        As[ak + 0][ar] = av.x; As[ak + 1][ar] = av.y;
        As[ak + 2][ar] = av.z; As[ak + 3][ar] = av.w;
        #pragma unroll
        for (int p = 0; p < 4; p++) {
            int r = (t >> 4) + p * 16, c = (t & 15) << 2;
            *(float4*)&W1s[r][c] = *(const float4*)&tw1[r * 64 + c];
            *(float4*)&W2s[r][c] = *(const float4*)&Wsl[r * 64 + c];
        }
    }
    __syncthreads();

    float acc1[4][4] = {}, acc2[4][4] = {};
    #pragma unroll 8
    for (int kk = 0; kk < 64; kk++) {
        float4 a4 = *(const float4*)&As[kk][ty << 2];
        float4 w1 = *(const float4*)&W1s[kk][c0];
        float4 w2 = *(const float4*)&W2s[kk][c0];
        const float a[4] = {a4.x, a4.y, a4.z, a4.w};
        const float u[4] = {w1.x, w1.y, w1.z, w1.w};
        const float v[4] = {w2.x, w2.y, w2.z, w2.w};
        #pragma unroll
        for (int i = 0; i < 4; i++)
            #pragma unroll
            for (int j = 0; j < 4; j++) {
                acc1[i][j] += a[i] * u[j];
                acc2[i][j] += a[i] * v[j];
            }
    }

    const float4 tb = *(const float4*)&tb1[c0];
    const float4 t2 = *(const float4*)&tw2[c0];
    const float4 bs = *(const float4*)&bsl[c0];
    const float tbv[4] = {tb.x, tb.y, tb.z, tb.w};
    const float t2v[4] = {t2.x, t2.y, t2.z, t2.w};
    const float bsv[4] = {bs.x, bs.y, bs.z, bs.w};
    const float tb2v = tb2[0];

    #pragma unroll
    for (int i = 0; i < 4; i++) {
        const int m = m0 + (ty << 2) + i;
        float p = 0.f;
        #pragma unroll
        for (int j = 0; j < 4; j++) p += gelu_f(acc1[i][j] + tbv[j]) * t2v[j];
        #pragma unroll
        for (int off = 8; off; off >>= 1) p += __shfl_xor_sync(0xffffffffu, p, off, 16);
        const float invT = 1.0f / fmaxf(gelu_f(p + tb2v) + bias[m & 7], 0.01f);

        const size_t gidx = (((size_t)(m >> 16) * Hc + (m & 7)) * Nc + ((m >> 3) & (Nc - 1))) * 64 + c0;
        const float4 gu = *(const float4*)&gumbel[gidx];
        float z[4];
        z[0] = (acc2[i][0] + bsv[0] + gu.x) * invT;
        z[1] = (acc2[i][1] + bsv[1] + gu.y) * invT;
        z[2] = (acc2[i][2] + bsv[2] + gu.z) * invT;
        z[3] = (acc2[i][3] + bsv[3] + gu.w) * invT;

        float mx = fmaxf(fmaxf(z[0], z[1]), fmaxf(z[2], z[3]));
        #pragma unroll
        for (int off = 8; off; off >>= 1) mx = fmaxf(mx, __shfl_xor_sync(0xffffffffu, mx, off, 16));
        float e0 = expf(z[0] - mx), e1 = expf(z[1] - mx), e2 = expf(z[2] - mx), e3 = expf(z[3] - mx);
        float s = e0 + e1 + e2 + e3;
        #pragma unroll
        for (int off = 8; off; off >>= 1) s += __shfl_xor_sync(0xffffffffu, s, off, 16);
        const float inv = 1.0f / s;
        *(float4*)&g_sw[(size_t)m * 64 + c0] = make_float4(e0 * inv, e1 * inv, e2 * inv, e3 * inv);
    }
}

// ---------------------------------------------------------------------------
__global__ __launch_bounds__(256) void dispatch_partial()
{
    int bh = blockIdx.x, s = blockIdx.y;
    int b = bh >> 3, h = bh & 7;
    int t = threadIdx.x;
    int tx = t & 15, ty = t >> 4;
    __shared__ float sws[32][64];
    __shared__ float xms[32][64];
    float acc[4][4] = {};
    float sn = 0.f;
    int nbase = s * SEGLEN;
    for (int ch = 0; ch < SEGLEN; ch += 32) {
        #pragma unroll
        for (int j = 0; j < 8; j++) {
            int idx = t + (j << 8);
            int r = idx >> 6, c = idx & 63;
            size_t nrow = (size_t)(b * Nc + nbase + ch + r);
            xms[r][c] = g_xm[nrow * Dc + h * 64 + c];
            sws[r][c] = g_sw[(nrow * Hc + h) * 64 + c];
        }
        __syncthreads();
        if (t < 64) {
            #pragma unroll
            for (int nn = 0; nn < 32; nn++) sn += sws[nn][t];
        }
        #pragma unroll 4
        for (int nn = 0; nn < 32; nn++) {
            float4 a4 = *(const float4*)&sws[nn][ty << 2];
            float4 b4 = *(const float4*)&xms[nn][tx << 2];
            acc[0][0] += a4.x*b4.x; acc[0][1] += a4.x*b4.y; acc[0][2] += a4.x*b4.z; acc[0][3] += a4.x*b4.w;
            acc[1][0] += a4.y*b4.x; acc[1][1] += a4.y*b4.y; acc[1][2] += a4.y*b4.z; acc[1][3] += a4.y*b4.w;
            acc[2][0] += a4.z*b4.x; acc[2][1] += a4.z*b4.y; acc[2][2] += a4.z*b4.z; acc[2][3] += a4.z*b4.w;
            acc[3][0] += a4.w*b4.x; acc[3][1] += a4.w*b4.y; acc[3][2] += a4.w*b4.z; acc[3][3] += a4.w*b4.w;
        }
        __syncthreads();
    }
    int base = (bh * SEGc + s) * 64;
    #pragma unroll
    for (int i = 0; i < 4; i++)
        #pragma unroll
        for (int j = 0; j < 4; j++)
            g_stp[(size_t)(base + (ty << 2) + i) * 64 + (tx << 2) + j] = acc[i][j];
    if (t < 64) g_snp[base + t] = sn;
}

// ---------------------------------------------------------------------------
// Fused reduce + slice attention (unchanged)
// ---------------------------------------------------------------------------
#define SA_R 68
#define SA_SMEM ((1+3+3+1)*64*SA_R*4)

__global__ __launch_bounds__(256) void slice_attn(
    const float* __restrict__ Wq, const float* __restrict__ Wk, const float* __restrict__ Wv)
{
    extern __shared__ float sm[];
    float* STt = sm;
    float* Wsm = STt + 64 * SA_R;
    float* Qt  = Wsm + 3 * 64 * SA_R;
    float* Kt  = Qt + 64 * SA_R;
    float* Vs  = Kt + 64 * SA_R;
    float* Pt  = Vs + 64 * SA_R;
    __shared__ float invsn[64];

    const int bh = blockIdx.x, t = threadIdx.x;
    const int tx = t & 15, ty = t >> 4;
    const int r4 = ty << 2, c4 = tx << 2;

    if (t < 64) {
        float v = 1e-5f;
        for (int s = 0; s < SEGc; s++) v += g_snp[(bh * SEGc + s) * 64 + t];
        invsn[t] = 1.0f / v;
    }
    const float* Wg[3] = {Wq, Wk, Wv};
    #pragma unroll
    for (int m = 0; m < 3; m++)
        #pragma unroll
        for (int e = 0; e < 4; e++) {
            int idx = (t + (e << 8)) << 2;
            int r = idx >> 6, c = idx & 63;
            float4 w = *(const float4*)&Wg[m][idx];
            *(float4*)&Wsm[(m * 64 + r) * SA_R + c] = w;
        }
    __syncthreads();

    #pragma unroll
    for (int e = 0; e < 16; e++) {
        int idx = t + (e << 8);
        float v = 0.f;
        #pragma unroll
        for (int s = 0; s < SEGc; s++) v += g_stp[(size_t)(bh * SEGc + s) * 4096 + idx];
        int tok = idx >> 6, d = idx & 63;
        STt[d * SA_R + tok] = v * invsn[tok];
    }
    __syncthreads();

    {
        float aq[4][4] = {}, ak[4][4] = {}, av[4][4] = {};
        #pragma unroll 4
        for (int d = 0; d < 64; d++) {
            float4 a4 = *(const float4*)&STt[d * SA_R + r4];
            float4 wq4 = *(const float4*)&Wsm[(0 * 64 + d) * SA_R + c4];
            float4 wk4 = *(const float4*)&Wsm[(1 * 64 + d) * SA_R + c4];
            float4 wv4 = *(const float4*)&Wsm[(2 * 64 + d) * SA_R + c4];
            const float a[4] = {a4.x, a4.y, a4.z, a4.w};
            const float uq[4] = {wq4.x, wq4.y, wq4.z, wq4.w};
            const float uk[4] = {wk4.x, wk4.y, wk4.z, wk4.w};
            const float uv[4] = {wv4.x, wv4.y, wv4.z, wv4.w};
            #pragma unroll
            for (int i = 0; i < 4; i++)
                #pragma unroll
                for (int j = 0; j < 4; j++) {
                    aq[i][j] += a[i] * uq[j];
                    ak[i][j] += a[i] * uk[j];
                    av[i][j] += a[i] * uv[j];
                }
        }
        __syncthreads();
        #pragma unroll
        for (int i = 0; i < 4; i++)
            #pragma unroll
            for (int j = 0; j < 4; j++) {
                Qt[(c4 + j) * SA_R + r4 + i] = aq[i][j];
                Kt[(c4 + j) * SA_R + r4 + i] = ak[i][j];
                Vs[(r4 + i) * SA_R + c4 + j] = av[i][j];
            }
    }
    __syncthreads();

    {
        float sc[4][4] = {};
        #pragma unroll 4
        for (int d = 0; d < 64; d++) {
            float4 a4 = *(const float4*)&Qt[d * SA_R + r4];
            float4 b4 = *(const float4*)&Kt[d * SA_R + c4];
            const float a[4] = {a4.x, a4.y, a4.z, a4.w};
            const float b[4] = {b4.x, b4.y, b4.z, b4.w};
            #pragma unroll
            for (int i = 0; i < 4; i++)
                #pragma unroll
                for (int j = 0; j < 4; j++) sc[i][j] += a[i] * b[j];
        }
        __syncthreads();
        #pragma unroll
        for (int i = 0; i < 4; i++)
            #pragma unroll
            for (int j = 0; j < 4; j++)
                Pt[(c4 + j) * SA_R + r4 + i] = sc[i][j] * 0.125f;
    }
    __syncthreads();

    if (t < 64) {
        float mx = -1e30f;
        #pragma unroll 8
        for (int j = 0; j < 64; j++) mx = fmaxf(mx, Pt[j * SA_R + t]);
        float sum = 0.f;
        #pragma unroll 8
        for (int j = 0; j < 64; j++) {
            float ee = expf(Pt[j * SA_R + t] - mx);
            Pt[j * SA_R + t] = ee;
            sum += ee;
        }
        float inv = 1.f / sum;
        #pragma unroll 8
        for (int j = 0; j < 64; j++) Pt[j * SA_R + t] *= inv;
    }
    __syncthreads();

    {
        float oc[4][4] = {};
        #pragma unroll 4
        for (int j = 0; j < 64; j++) {
            float4 a4 = *(const float4*)&Pt[j * SA_R + r4];
            float4 b4 = *(const float4*)&Vs[j * SA_R + c4];
            const float a[4] = {a4.x, a4.y, a4.z, a4.w};
            const float b[4] = {b4.x, b4.y, b4.z, b4.w};
            #pragma unroll
            for (int i = 0; i < 4; i++)
                #pragma unroll
                for (int jj = 0; jj < 4; jj++) oc[i][jj] += a[i] * b[jj];
        }
        #pragma unroll
        for (int i = 0; i < 4; i++)
            #pragma unroll
            for (int j = 0; j < 4; j++)
                g_ost[(size_t)bh * 4096 + (r4 + i) * 64 + c4 + j] = oc[i][j];
    }
}

// ---------------------------------------------------------------------------
// Scatter back: writes fp16 y
// ---------------------------------------------------------------------------
__global__ __launch_bounds__(256) void scatter_back()
{
    int tile = blockIdx.x;
    int h  = tile & 7;
    int nt = (tile >> 3) & 255;
    int b  = tile >> 11;
    int bh = b * Hc + h;
    int t = threadIdx.x;
    __shared__ float osh[64][64];
    __shared__ float swsh[32][64];
    #pragma unroll
    for (int e = 0; e < 16; e++) {
        int idx = t + (e << 8);
        osh[idx >> 6][idx & 63] = g_ost[(size_t)bh * 4096 + idx];
    }
    #pragma unroll
    for (int e = 0; e < 8; e++) {
        int idx = t + (e << 8);
        int r = idx >> 6, c = idx & 63;
        swsh[r][c] = g_sw[(((size_t)(b * Nc + nt * 32 + r)) * Hc + h) * 64 + c];
    }
    __syncthreads();
    int tt = t >> 3, c0 = (t & 7) << 3;
    float o[8] = {};
    for (int g = 0; g < 64; g++) {
        float swv = swsh[tt][g];
        #pragma unroll
        for (int e = 0; e < 8; e++) o[e] += swv * osh[g][c0 + e];
    }
    int n = nt * 32 + tt;
    size_t base = ((size_t)(b * Nc + n)) * Dc + h * 64 + c0;
    #pragma unroll
    for (int e = 0; e < 8; e += 2)
        *(__half2*)&g_yh[base + e] = __floats2half2_rn(o[e], o[e + 1]);
}

// ---------------------------------------------------------------------------
// LayerNorm: reads g_o2, writes fp16 g_lnh
// ---------------------------------------------------------------------------
__global__ __launch_bounds__(128) void ln_k(
    const float* __restrict__ gam, const float* __restrict__ bet)
{
    int row = blockIdx.x, t = threadIdx.x;
    const float4 v = *(const float4*)&g_o2[(size_t)row * Dc + (t << 2)];
    float s = v.x + v.y + v.z + v.w;
    __shared__ float rs[4];
    #pragma unroll
    for (int off = 16; off; off >>= 1) s += __shfl_xor_sync(0xffffffffu, s, off);
    int w = t >> 5;
    if ((t & 31) == 0) rs[w] = s;
    __syncthreads();
    float mean = (rs[0] + rs[1] + rs[2] + rs[3]) * (1.f / 512.f);
    float dx = v.x - mean, dy = v.y - mean, dz = v.z - mean, dw = v.w - mean;
    float q = dx*dx + dy*dy + dz*dz + dw*dw;
    #pragma unroll
    for (int off = 16; off; off >>= 1) q += __shfl_xor_sync(0xffffffffu, q, off);
    __syncthreads();
    if ((t & 31) == 0) rs[w] = q;
    __syncthreads();
    float var = (rs[0] + rs[1] + rs[2] + rs[3]) * (1.f / 512.f);
    float inv = rsqrtf(var + 1e-5f);
    float4 gv = *(const float4*)&gam[t << 2];
    float4 bv = *(const float4*)&bet[t << 2];
    size_t base = (size_t)row * Dc + (t << 2);
    *(__half2*)&g_lnh[base]     = __floats2half2_rn(dx * inv * gv.x + bv.x, dy * inv * gv.y + bv.y);
    *(__half2*)&g_lnh[base + 2] = __floats2half2_rn(dz * inv * gv.z + bv.z, dw * inv * gv.w + bv.w);
}

// ---------------------------------------------------------------------------
extern "C" void kernel_launch(void* const* d_in, const int* in_sizes, int n_in,
                              void* d_out, int out_size)
{
    const float* x      = (const float*)d_in[0];
    const float* gumbel = (const float*)d_in[1];
    const float* Wx     = (const float*)d_in[2];
    const float* bx     = (const float*)d_in[3];
    const float* tw1    = (const float*)d_in[4];
    const float* tb1    = (const float*)d_in[5];
    const float* tw2    = (const float*)d_in[6];
    const float* tb2    = (const float*)d_in[7];
    const float* bias   = (const float*)d_in[8];
    const float* Wsl    = (const float*)d_in[9];
    const float* bsl    = (const float*)d_in[10];
    const float* Wq     = (const float*)d_in[11];
    const float* Wk     = (const float*)d_in[12];
    const float* Wv     = (const float*)d_in[13];
    const float* Wp     = (const float*)d_in[14];
    const float* bp     = (const float*)d_in[15];
    const float* ln2g   = (const float*)d_in[16];
    const float* ln2b   = (const float*)d_in[17];
    const float* W1     = (const float*)d_in[18];
    const float* b1     = (const float*)d_in[19];
    const float* W2     = (const float*)d_in[20];
    const float* b2     = (const float*)d_in[21];
    float* out = (float*)d_out;

    float *xm, *o2;
    __half *xh, *yh, *lnh, *midh, *bth;
    cudaGetSymbolAddress((void**)&xm,   g_xm);
    cudaGetSymbolAddress((void**)&o2,   g_o2);
    cudaGetSymbolAddress((void**)&xh,   g_xh);
    cudaGetSymbolAddress((void**)&yh,   g_yh);
    cudaGetSymbolAddress((void**)&lnh,  g_lnh);
    cudaGetSymbolAddress((void**)&midh, g_midh);
    cudaGetSymbolAddress((void**)&bth,  g_bth);

    cudaFuncSetAttribute((const void*)gemm_h16<0,float>,  cudaFuncAttributeMaxDynamicSharedMemorySize, GEMM_SMEM);
    cudaFuncSetAttribute((const void*)gemm_h16<1,float>,  cudaFuncAttributeMaxDynamicSharedMemorySize, GEMM_SMEM);
    cudaFuncSetAttribute((const void*)gemm_h16<2,__half>, cudaFuncAttributeMaxDynamicSharedMemorySize, GEMM_SMEM);
    cudaFuncSetAttribute((const void*)slice_attn,         cudaFuncAttributeMaxDynamicSharedMemorySize, SA_SMEM);

    // 0. conversions
    convert_f2h<<<(Mrows*(size_t)Dc)/2048, 256>>>(x, xh);
    dim3 tb32(32, 8);
    transpose_k<<<dim3(Dc/32,  Dc/32),  tb32>>>(Wx, bth + BT_WX, Dc,   Dc);
    transpose_k<<<dim3(Dc/32,  Dc/32),  tb32>>>(Wp, bth + BT_WP, Dc,   Dc);
    transpose_k<<<dim3(HIDc/32, Dc/32), tb32>>>(W1, bth + BT_W1, Dc,   HIDc);
    transpose_k<<<dim3(Dc/32, HIDc/32), tb32>>>(W2, bth + BT_W2, HIDc, Dc);

    // 1. xm = x @ Wx + bx  (fp32 out)
    gemm_h16<0,float><<<dim3(Dc/128, Mrows/128), 256, GEMM_SMEM>>>(xh, bth + BT_WX, bx, nullptr, xm, Dc, Dc);
    // 2. fused router -> g_sw
    fused_router<<<MH/64, 256>>>(tw1, tb1, tw2, tb2, bias, Wsl, bsl, gumbel);
    // 3. dispatch
    dispatch_partial<<<dim3(Bc*Hc, SEGc), 256>>>();
    // 4. reduce + slice attention
    slice_attn<<<Bc*Hc, 256, SA_SMEM>>>(Wq, Wk, Wv);
    // 5. scatter back (fp16 y)
    scatter_back<<<Bc*(Nc/32)*Hc, 256>>>();
    // 6. o2 = y @ Wp + bp + x
    gemm_h16<1,float><<<dim3(Dc/128, Mrows/128), 256, GEMM_SMEM>>>(yh, bth + BT_WP, bp, x, o2, Dc, Dc);
    // 7. layernorm (fp16 out)
    ln_k<<<Mrows, 128>>>(ln2g, ln2b);
    // 8. mid = gelu(ln @ W1 + b1)  (fp16 out)
    gemm_h16<2,__half><<<dim3(HIDc/128, Mrows/128), 256, GEMM_SMEM>>>(lnh, bth + BT_W1, b1, nullptr, midh, Dc, HIDc);
    // 9. out = mid @ W2 + b2 + x
    gemm_h16<1,float><<<dim3(Dc/128, Mrows/128), 256, GEMM_SMEM>>>(midh, bth + BT_W2, b2, x, out, HIDc, Dc);
}

// round 7
// speedup vs baseline: 4.9131x; 1.5510x over previous
#include <cuda_runtime.h>
#include <cuda_fp16.h>
#include <math.h>
#include <stdint.h>

// Problem constants
#define Bc   4
#define Nc   8192
#define Dc   512
#define Hc   8
#define DHc  64
#define Kc   64
#define HIDc 1024
#define Mrows (Bc*Nc)        // 32768
#define MH    (Mrows*Hc)     // 262144 token-heads
#define SEGc  16
#define SEGLEN (Nc/SEGc)     // 512

// Scratch (device globals; no allocation allowed)
__device__ float  g_stp [Bc*Hc*SEGc*Kc*DHc];
__device__ float  g_snp [Bc*Hc*SEGc*Kc];
__device__ float  g_o2  [(size_t)Mrows*Dc];
// fp16 operands
__device__ __half g_xh  [(size_t)Mrows*Dc];     // x as fp16
__device__ __half g_xmh [(size_t)Mrows*Dc];     // xm as fp16 ([MH][64] view)
__device__ __half g_swh [(size_t)MH*Kc];        // router weights fp16
__device__ __half g_osth[Bc*Hc*Kc*DHc];         // attn out, transposed [c][g], fp16
__device__ __half g_yh  [(size_t)Mrows*Dc];     // scatter output
__device__ __half g_lnh [(size_t)Mrows*Dc];     // layernorm output
__device__ __half g_midh[(size_t)Mrows*HIDc];   // MLP mid
// transposed fp16 weights [N][K]
#define BT_WX 0
#define BT_WP 262144
#define BT_W1 524288
#define BT_W2 1048576
__device__ __half g_bth [1572864];
__device__ __half g_tw1T[64*64];
__device__ __half g_wslT[64*64];

__device__ __forceinline__ float gelu_f(float x) {
    return 0.5f * x * (1.0f + erff(0.70710678118654752440f * x));
}
__device__ __forceinline__ unsigned s2u(const void* p) {
    return (unsigned)__cvta_generic_to_shared(p);
}
__device__ __forceinline__ void cpa16(void* s, const void* g) {
    unsigned sa = s2u(s);
    asm volatile("cp.async.cg.shared.global [%0], [%1], 16;\n" :: "r"(sa), "l"(g));
}
#define CP_COMMIT() asm volatile("cp.async.commit_group;\n")
#define CP_WAIT2()  asm volatile("cp.async.wait_group 2;\n")
#define CP_WAIT1()  asm volatile("cp.async.wait_group 1;\n")
#define CP_WAIT0()  asm volatile("cp.async.wait_group 0;\n")

__device__ __forceinline__ void mma_f16(float* c, const unsigned* a, const unsigned* b) {
    asm volatile(
        "mma.sync.aligned.m16n8k16.row.col.f32.f16.f16.f32 "
        "{%0,%1,%2,%3}, {%4,%5,%6,%7}, {%8,%9}, {%0,%1,%2,%3};\n"
        : "+f"(c[0]), "+f"(c[1]), "+f"(c[2]), "+f"(c[3])
        : "r"(a[0]), "r"(a[1]), "r"(a[2]), "r"(a[3]), "r"(b[0]), "r"(b[1]));
}
__device__ __forceinline__ void ldsm4(unsigned* r, const __half* p) {
    unsigned a = s2u(p);
    asm volatile("ldmatrix.sync.aligned.m8n8.x4.shared.b16 {%0,%1,%2,%3}, [%4];\n"
        : "=r"(r[0]), "=r"(r[1]), "=r"(r[2]), "=r"(r[3]) : "r"(a));
}
__device__ __forceinline__ void store2(float* C, size_t idx, float v0, float v1) {
    *(float2*)&C[idx] = make_float2(v0, v1);
}
__device__ __forceinline__ void store2(__half* C, size_t idx, float v0, float v1) {
    *(__half2*)&C[idx] = __floats2half2_rn(v0, v1);
}

// ---------------------------------------------------------------------------
// FP16 tensor-core GEMM (unchanged from R6)
// ---------------------------------------------------------------------------
#define BKh 32
#define HS  40
#define STAGEH (128*HS)
#define NSTh 3
#define GEMM_SMEM (NSTh*2*STAGEH*2)

template<int EPI, typename OutT>
__global__ __launch_bounds__(256, 2) void gemm_h16(
    const __half* __restrict__ A, const __half* __restrict__ Bt,
    const float* __restrict__ bias, const float* __restrict__ res,
    OutT* __restrict__ C, int Kd, int Nd)
{
    extern __shared__ __half smh[];
    const int t = threadIdx.x;
    const int warp = t >> 5, lane = t & 31;
    const int g = lane >> 2, q = lane & 3;
    const int wm = (warp >> 2) << 6;
    const int wn = (warp & 3) << 5;
    const int m0 = blockIdx.y << 7;
    const int n0 = blockIdx.x << 7;
    const int lrow = lane & 15;
    const int lkof = (lane >> 4) << 3;
    const int r128 = t >> 1;
    const int hoff = (t & 1) << 4;
    const __half* Ap = A  + (size_t)(m0 + r128) * Kd + hoff;
    const __half* Bp = Bt + (size_t)(n0 + r128) * Kd + hoff;
    float acc[4][4][4] = {};

    auto load_tile = [&](int buf, int k0) {
        __half* As = smh + buf * 2 * STAGEH;
        __half* Bs = As + STAGEH;
        cpa16(As + r128 * HS + hoff,     Ap + k0);
        cpa16(As + r128 * HS + hoff + 8, Ap + k0 + 8);
        cpa16(Bs + r128 * HS + hoff,     Bp + k0);
        cpa16(Bs + r128 * HS + hoff + 8, Bp + k0 + 8);
        CP_COMMIT();
    };

    const int nk = Kd / BKh;
    load_tile(0, 0);
    load_tile(1, BKh);

    for (int it = 0; it < nk; ++it) {
        if (it + 2 < nk)       { load_tile((it + 2) % NSTh, (it + 2) * BKh); CP_WAIT2(); }
        else if (it + 2 == nk) { CP_WAIT1(); }
        else                   { CP_WAIT0(); }
        __syncthreads();
        const __half* As = smh + (it % NSTh) * 2 * STAGEH;
        const __half* Bs = As + STAGEH;
        #pragma unroll
        for (int ks = 0; ks < 2; ks++) {
            const int kb = ks << 4;
            unsigned af[4][4], bf[4][2];
            #pragma unroll
            for (int mt = 0; mt < 4; mt++)
                ldsm4(af[mt], As + (wm + mt * 16 + lrow) * HS + kb + lkof);
            #pragma unroll
            for (int nt = 0; nt < 4; nt++) {
                const __half* bp = Bs + (wn + nt * 8 + g) * HS + kb + (q << 1);
                bf[nt][0] = *(const unsigned*)bp;
                bf[nt][1] = *(const unsigned*)(bp + 8);
            }
            #pragma unroll
            for (int mt = 0; mt < 4; mt++)
                #pragma unroll
                for (int nt = 0; nt < 4; nt++)
                    mma_f16(acc[mt][nt], af[mt], bf[nt]);
        }
        __syncthreads();
    }

    #pragma unroll
    for (int nt = 0; nt < 4; nt++) {
        const int col = n0 + wn + nt * 8 + (q << 1);
        const float b0 = bias[col], b1 = bias[col + 1];
        #pragma unroll
        for (int mt = 0; mt < 4; mt++) {
            int r0 = m0 + wm + mt * 16 + g;
            int r1 = r0 + 8;
            float v0 = acc[mt][nt][0] + b0, v1 = acc[mt][nt][1] + b1;
            float v2 = acc[mt][nt][2] + b0, v3 = acc[mt][nt][3] + b1;
            if (EPI == 2) { v0 = gelu_f(v0); v1 = gelu_f(v1); v2 = gelu_f(v2); v3 = gelu_f(v3); }
            if (EPI == 1) {
                const float2 ra = *(const float2*)&res[(size_t)r0 * Nd + col];
                const float2 rb = *(const float2*)&res[(size_t)r1 * Nd + col];
                v0 += ra.x; v1 += ra.y; v2 += rb.x; v3 += rb.y;
            }
            store2(C, (size_t)r0 * Nd + col, v0, v1);
            store2(C, (size_t)r1 * Nd + col, v2, v3);
        }
    }
}

// ---------------------------------------------------------------------------
__global__ __launch_bounds__(256) void convert_f2h(
    const float* __restrict__ S, __half* __restrict__ D)
{
    size_t i = ((size_t)blockIdx.x * 256 + threadIdx.x) * 8;
    float4 a = *(const float4*)&S[i];
    float4 b = *(const float4*)&S[i + 4];
    *(__half2*)&D[i]     = __floats2half2_rn(a.x, a.y);
    *(__half2*)&D[i + 2] = __floats2half2_rn(a.z, a.w);
    *(__half2*)&D[i + 4] = __floats2half2_rn(b.x, b.y);
    *(__half2*)&D[i + 6] = __floats2half2_rn(b.z, b.w);
}

__global__ __launch_bounds__(256) void transpose_k(
    const float* __restrict__ S, __half* __restrict__ D, int R, int Ccol)
{
    __shared__ float tl[32][33];
    int c0 = blockIdx.x << 5, r0 = blockIdx.y << 5;
    int x = threadIdx.x, y = threadIdx.y;
    #pragma unroll
    for (int j = 0; j < 32; j += 8)
        tl[y + j][x] = S[(size_t)(r0 + y + j) * Ccol + c0 + x];
    __syncthreads();
    #pragma unroll
    for (int j = 0; j < 32; j += 8)
        D[(size_t)(c0 + y + j) * R + r0 + x] = __float2half_rn(tl[x][y + j]);
}

// ---------------------------------------------------------------------------
// Router on tensor cores. Block = 128 token-head rows, 8 warps x 16 rows.
// A = xmh [m][64], B = tw1T/WslT [k][64]. Softmax via quad shuffles.
// ---------------------------------------------------------------------------
__global__ __launch_bounds__(256) void router_mma(
    const float* __restrict__ tb1, const float* __restrict__ tw2,
    const float* __restrict__ tb2, const float* __restrict__ bias,
    const float* __restrict__ bsl, const float* __restrict__ gumbel)
{
    __shared__ __half Xs[128*72];
    __shared__ __half W1s[64*72];
    __shared__ __half W2s[64*72];
    __shared__ float tb1s[64], tw2s[64], bsls[64];
    const int t = threadIdx.x, w = t >> 5, lane = t & 31;
    const int g = lane >> 2, q = lane & 3;
    const int m0 = blockIdx.x << 7;

    #pragma unroll
    for (int e = 0; e < 4; e++) {
        int sg = t + (e << 8);
        int r = sg >> 3, o = (sg & 7) << 3;
        cpa16(&Xs[r*72 + o], &g_xmh[(size_t)(m0 + r)*64 + o]);
    }
    #pragma unroll
    for (int e = 0; e < 2; e++) {
        int sg = t + (e << 8);
        int r = sg >> 3, o = (sg & 7) << 3;
        cpa16(&W1s[r*72 + o], &g_tw1T[r*64 + o]);
        cpa16(&W2s[r*72 + o], &g_wslT[r*64 + o]);
    }
    if (t < 64) { tb1s[t] = tb1[t]; tw2s[t] = tw2[t]; bsls[t] = bsl[t]; }
    CP_COMMIT(); CP_WAIT0();
    __syncthreads();

    unsigned af[4][4];
    #pragma unroll
    for (int ks = 0; ks < 4; ks++)
        ldsm4(af[ks], &Xs[(w*16 + (lane & 15))*72 + ks*16 + ((lane >> 4) << 3)]);

    float a1[8][4] = {}, a2[8][4] = {};
    #pragma unroll
    for (int nt = 0; nt < 8; nt++)
        #pragma unroll
        for (int ks = 0; ks < 4; ks++) {
            const __half* p1 = &W1s[(nt*8 + g)*72 + ks*16 + (q << 1)];
            const __half* p2 = &W2s[(nt*8 + g)*72 + ks*16 + (q << 1)];
            unsigned b1f[2] = {*(const unsigned*)p1, *(const unsigned*)(p1 + 8)};
            unsigned b2f[2] = {*(const unsigned*)p2, *(const unsigned*)(p2 + 8)};
            mma_f16(a1[nt], af[ks], b1f);
            mma_f16(a2[nt], af[ks], b2f);
        }

    const float tb2v = tb2[0];
    #pragma unroll
    for (int rr = 0; rr < 2; rr++) {
        const int m = m0 + w*16 + g + rr*8;
        const int h = m & 7;
        const int n = (m >> 3) & (Nc - 1);
        const int b = m >> 16;
        float p = 0.f;
        #pragma unroll
        for (int nt = 0; nt < 8; nt++) {
            int col = nt*8 + (q << 1);
            p += gelu_f(a1[nt][rr*2 + 0] + tb1s[col])     * tw2s[col];
            p += gelu_f(a1[nt][rr*2 + 1] + tb1s[col + 1]) * tw2s[col + 1];
        }
        p += __shfl_xor_sync(0xffffffffu, p, 1);
        p += __shfl_xor_sync(0xffffffffu, p, 2);
        const float invT = 1.0f / fmaxf(gelu_f(p + tb2v) + bias[h], 0.01f);

        const size_t gbase = (((size_t)b * Hc + h) * Nc + n) * 64;
        float z[8][2];
        float mx = -1e30f;
        #pragma unroll
        for (int nt = 0; nt < 8; nt++) {
            int col = nt*8 + (q << 1);
            float2 gu = *(const float2*)&gumbel[gbase + col];
            z[nt][0] = (a2[nt][rr*2 + 0] + bsls[col]     + gu.x) * invT;
            z[nt][1] = (a2[nt][rr*2 + 1] + bsls[col + 1] + gu.y) * invT;
            mx = fmaxf(mx, fmaxf(z[nt][0], z[nt][1]));
        }
        mx = fmaxf(mx, __shfl_xor_sync(0xffffffffu, mx, 1));
        mx = fmaxf(mx, __shfl_xor_sync(0xffffffffu, mx, 2));
        float sum = 0.f;
        #pragma unroll
        for (int nt = 0; nt < 8; nt++) {
            z[nt][0] = expf(z[nt][0] - mx);
            z[nt][1] = expf(z[nt][1] - mx);
            sum += z[nt][0] + z[nt][1];
        }
        sum += __shfl_xor_sync(0xffffffffu, sum, 1);
        sum += __shfl_xor_sync(0xffffffffu, sum, 2);
        const float inv = 1.0f / sum;
        #pragma unroll
        for (int nt = 0; nt < 8; nt++) {
            int col = nt*8 + (q << 1);
            *(__half2*)&g_swh[(size_t)m*64 + col] = __floats2half2_rn(z[nt][0]*inv, z[nt][1]*inv);
        }
    }
}

// ---------------------------------------------------------------------------
// Dispatch on tensor cores: st_part[k][c] = sum_n sw[n][k]*xm[n][c].
// A = sw^T, B = xm^T, both transposed at STS time. grid (32 bh, 16 seg).
// ---------------------------------------------------------------------------
__global__ __launch_bounds__(256) void dispatch_mma()
{
    __shared__ __half swT[64*72];
    __shared__ __half xmT[64*72];
    const int t = threadIdx.x, w = t >> 5, lane = t & 31;
    const int g = lane >> 2, q = lane & 3;
    const int bh = blockIdx.x, s = blockIdx.y;
    const int b = bh >> 3, h = bh & 7;
    const int wm = (w & 3) << 4, wn = (w >> 2) << 5;
    const int nl = t & 63, k0 = (t >> 6) << 4;

    float acc[4][4] = {};
    float sn = 0.f;

    for (int ch = 0; ch < 8; ch++) {
        const int nb = s * SEGLEN + ch * 64;
        const size_t mrow = (size_t)(b * Nc + nb + nl) * Hc + h;
        const __half* sp = &g_swh[mrow * 64 + k0];
        const __half* xp = &g_xmh[mrow * 64 + k0];
        __half ta[16], tx[16];
        *(uint4*)ta       = *(const uint4*)sp;
        *(uint4*)(ta + 8) = *(const uint4*)(sp + 8);
        *(uint4*)tx       = *(const uint4*)xp;
        *(uint4*)(tx + 8) = *(const uint4*)(xp + 8);
        #pragma unroll
        for (int i = 0; i < 16; i++) {
            swT[(k0 + i)*72 + nl] = ta[i];
            xmT[(k0 + i)*72 + nl] = tx[i];
        }
        __syncthreads();

        if (t < 64) {
            const __half2* rowp = (const __half2*)&swT[t*72];
            float lsn = 0.f;
            #pragma unroll
            for (int i = 0; i < 32; i++) {
                float2 f = __half22float2(rowp[i]);
                lsn += f.x + f.y;
            }
            sn += lsn;
        }
        unsigned af[4][4];
        #pragma unroll
        for (int ks = 0; ks < 4; ks++)
            ldsm4(af[ks], &swT[(wm + (lane & 15))*72 + ks*16 + ((lane >> 4) << 3)]);
        #pragma unroll
        for (int nt = 0; nt < 4; nt++)
            #pragma unroll
            for (int ks = 0; ks < 4; ks++) {
                const __half* bp = &xmT[(wn + nt*8 + g)*72 + ks*16 + (q << 1)];
                unsigned bf[2] = {*(const unsigned*)bp, *(const unsigned*)(bp + 8)};
                mma_f16(acc[nt], af[ks], bf);
            }
        __syncthreads();
    }

    const int base = bh * SEGc + s;
    #pragma unroll
    for (int nt = 0; nt < 4; nt++) {
        int col = wn + nt*8 + (q << 1);
        *(float2*)&g_stp[(size_t)base*4096 + (wm + g)*64 + col]     = make_float2(acc[nt][0], acc[nt][1]);
        *(float2*)&g_stp[(size_t)base*4096 + (wm + g + 8)*64 + col] = make_float2(acc[nt][2], acc[nt][3]);
    }
    if (t < 64) g_snp[base*64 + t] = sn;
}

// ---------------------------------------------------------------------------
// Fused reduce + slice attention (writes g_osth fp16 transposed [c][g])
// ---------------------------------------------------------------------------
#define SA_R 68
#define SA_SMEM ((1+3+3+1)*64*SA_R*4)

__global__ __launch_bounds__(256) void slice_attn(
    const float* __restrict__ Wq, const float* __restrict__ Wk, const float* __restrict__ Wv)
{
    extern __shared__ float sm[];
    float* STt = sm;
    float* Wsm = STt + 64 * SA_R;
    float* Qt  = Wsm + 3 * 64 * SA_R;
    float* Kt  = Qt + 64 * SA_R;
    float* Vs  = Kt + 64 * SA_R;
    float* Pt  = Vs + 64 * SA_R;
    __shared__ float invsn[64];

    const int bh = blockIdx.x, t = threadIdx.x;
    const int tx = t & 15, ty = t >> 4;
    const int r4 = ty << 2, c4 = tx << 2;

    if (t < 64) {
        float v = 1e-5f;
        for (int s = 0; s < SEGc; s++) v += g_snp[(bh * SEGc + s) * 64 + t];
        invsn[t] = 1.0f / v;
    }
    const float* Wg[3] = {Wq, Wk, Wv};
    #pragma unroll
    for (int m = 0; m < 3; m++)
        #pragma unroll
        for (int e = 0; e < 4; e++) {
            int idx = (t + (e << 8)) << 2;
            int r = idx >> 6, c = idx & 63;
            float4 wv4 = *(const float4*)&Wg[m][idx];
            *(float4*)&Wsm[(m * 64 + r) * SA_R + c] = wv4;
        }
    __syncthreads();

    #pragma unroll
    for (int e = 0; e < 16; e++) {
        int idx = t + (e << 8);
        float v = 0.f;
        #pragma unroll
        for (int s = 0; s < SEGc; s++) v += g_stp[(size_t)(bh * SEGc + s) * 4096 + idx];
        int tok = idx >> 6, d = idx & 63;
        STt[d * SA_R + tok] = v * invsn[tok];
    }
    __syncthreads();

    {
        float aq[4][4] = {}, ak[4][4] = {}, av[4][4] = {};
        #pragma unroll 4
        for (int d = 0; d < 64; d++) {
            float4 a4 = *(const float4*)&STt[d * SA_R + r4];
            float4 wq4 = *(const float4*)&Wsm[(0 * 64 + d) * SA_R + c4];
            float4 wk4 = *(const float4*)&Wsm[(1 * 64 + d) * SA_R + c4];
            float4 wv4 = *(const float4*)&Wsm[(2 * 64 + d) * SA_R + c4];
            const float a[4] = {a4.x, a4.y, a4.z, a4.w};
            const float uq[4] = {wq4.x, wq4.y, wq4.z, wq4.w};
            const float uk[4] = {wk4.x, wk4.y, wk4.z, wk4.w};
            const float uv[4] = {wv4.x, wv4.y, wv4.z, wv4.w};
            #pragma unroll
            for (int i = 0; i < 4; i++)
                #pragma unroll
                for (int j = 0; j < 4; j++) {
                    aq[i][j] += a[i] * uq[j];
                    ak[i][j] += a[i] * uk[j];
                    av[i][j] += a[i] * uv[j];
                }
        }
        __syncthreads();
        #pragma unroll
        for (int i = 0; i < 4; i++)
            #pragma unroll
            for (int j = 0; j < 4; j++) {
                Qt[(c4 + j) * SA_R + r4 + i] = aq[i][j];
                Kt[(c4 + j) * SA_R + r4 + i] = ak[i][j];
                Vs[(r4 + i) * SA_R + c4 + j] = av[i][j];
            }
    }
    __syncthreads();

    {
        float sc[4][4] = {};
        #pragma unroll 4
        for (int d = 0; d < 64; d++) {
            float4 a4 = *(const float4*)&Qt[d * SA_R + r4];
            float4 b4 = *(const float4*)&Kt[d * SA_R + c4];
            const float a[4] = {a4.x, a4.y, a4.z, a4.w};
            const float b[4] = {b4.x, b4.y, b4.z, b4.w};
            #pragma unroll
            for (int i = 0; i < 4; i++)
                #pragma unroll
                for (int j = 0; j < 4; j++) sc[i][j] += a[i] * b[j];
        }
        __syncthreads();
        #pragma unroll
        for (int i = 0; i < 4; i++)
            #pragma unroll
            for (int j = 0; j < 4; j++)
                Pt[(c4 + j) * SA_R + r4 + i] = sc[i][j] * 0.125f;
    }
    __syncthreads();

    if (t < 64) {
        float mx = -1e30f;
        #pragma unroll 8
        for (int j = 0; j < 64; j++) mx = fmaxf(mx, Pt[j * SA_R + t]);
        float sum = 0.f;
        #pragma unroll 8
        for (int j = 0; j < 64; j++) {
            float ee = expf(Pt[j * SA_R + t] - mx);
            Pt[j * SA_R + t] = ee;
            sum += ee;
        }
        float inv = 1.f / sum;
        #pragma unroll 8
        for (int j = 0; j < 64; j++) Pt[j * SA_R + t] *= inv;
    }
    __syncthreads();

    {
        float oc[4][4] = {};
        #pragma unroll 4
        for (int j = 0; j < 64; j++) {
            float4 a4 = *(const float4*)&Pt[j * SA_R + r4];
            float4 b4 = *(const float4*)&Vs[j * SA_R + c4];
            const float a[4] = {a4.x, a4.y, a4.z, a4.w};
            const float b[4] = {b4.x, b4.y, b4.z, b4.w};
            #pragma unroll
            for (int i = 0; i < 4; i++)
                #pragma unroll
                for (int jj = 0; jj < 4; jj++) oc[i][jj] += a[i] * b[jj];
        }
        // write transposed fp16: osth[c][g]
        #pragma unroll
        for (int i = 0; i < 4; i++)
            #pragma unroll
            for (int j = 0; j < 4; j++)
                g_osth[(size_t)bh * 4096 + (c4 + j) * 64 + (r4 + i)] = __float2half_rn(oc[i][j]);
    }
}

// ---------------------------------------------------------------------------
// Scatter on tensor cores: y[n][c] = sum_g sw[n][g] * ost[g][c].
// A = sw rows (natural), B = osth [c][g]. grid = B*H*64 tiles of 128 n.
// ---------------------------------------------------------------------------
__global__ __launch_bounds__(256) void scatter_mma()
{
    __shared__ __half As[128*72];
    __shared__ __half Bs[64*72];
    const int t = threadIdx.x, w = t >> 5, lane = t & 31;
    const int g = lane >> 2, q = lane & 3;
    const int tile = blockIdx.x;
    const int h = tile & 7, nt128 = (tile >> 3) & 63, b = tile >> 9;
    const int bh = b * 8 + h, n0 = nt128 << 7;

    #pragma unroll
    for (int e = 0; e < 2; e++) {
        int sg = t + (e << 8);
        int r = sg >> 3, o = (sg & 7) << 3;
        cpa16(&Bs[r*72 + o], &g_osth[(size_t)bh * 4096 + r*64 + o]);
    }
    #pragma unroll
    for (int e = 0; e < 4; e++) {
        int sg = t + (e << 8);
        int r = sg >> 3, o = (sg & 7) << 3;
        cpa16(&As[r*72 + o], &g_swh[((size_t)(b * Nc + n0 + r) * Hc + h) * 64 + o]);
    }
    CP_COMMIT(); CP_WAIT0();
    __syncthreads();

    unsigned af[4][4];
    #pragma unroll
    for (int ks = 0; ks < 4; ks++)
        ldsm4(af[ks], &As[(w*16 + (lane & 15))*72 + ks*16 + ((lane >> 4) << 3)]);
    float acc[8][4] = {};
    #pragma unroll
    for (int nt = 0; nt < 8; nt++)
        #pragma unroll
        for (int ks = 0; ks < 4; ks++) {
            const __half* bp = &Bs[(nt*8 + g)*72 + ks*16 + (q << 1)];
            unsigned bf[2] = {*(const unsigned*)bp, *(const unsigned*)(bp + 8)};
            mma_f16(acc[nt], af[ks], bf);
        }
    #pragma unroll
    for (int nt = 0; nt < 8; nt++) {
        int col = nt*8 + (q << 1);
        int r0 = n0 + w*16 + g;
        *(__half2*)&g_yh[(size_t)(b * Nc + r0) * Dc + h*64 + col] =
            __floats2half2_rn(acc[nt][0], acc[nt][1]);
        *(__half2*)&g_yh[(size_t)(b * Nc + r0 + 8) * Dc + h*64 + col] =
            __floats2half2_rn(acc[nt][2], acc[nt][3]);
    }
}

// ---------------------------------------------------------------------------
__global__ __launch_bounds__(128) void ln_k(
    const float* __restrict__ gam, const float* __restrict__ bet)
{
    int row = blockIdx.x, t = threadIdx.x;
    const float4 v = *(const float4*)&g_o2[(size_t)row * Dc + (t << 2)];
    float s = v.x + v.y + v.z + v.w;
    __shared__ float rs[4];
    #pragma unroll
    for (int off = 16; off; off >>= 1) s += __shfl_xor_sync(0xffffffffu, s, off);
    int w = t >> 5;
    if ((t & 31) == 0) rs[w] = s;
    __syncthreads();
    float mean = (rs[0] + rs[1] + rs[2] + rs[3]) * (1.f / 512.f);
    float dx = v.x - mean, dy = v.y - mean, dz = v.z - mean, dw = v.w - mean;
    float qv = dx*dx + dy*dy + dz*dz + dw*dw;
    #pragma unroll
    for (int off = 16; off; off >>= 1) qv += __shfl_xor_sync(0xffffffffu, qv, off);
    __syncthreads();
    if ((t & 31) == 0) rs[w] = qv;
    __syncthreads();
    float var = (rs[0] + rs[1] + rs[2] + rs[3]) * (1.f / 512.f);
    float inv = rsqrtf(var + 1e-5f);
    float4 gv = *(const float4*)&gam[t << 2];
    float4 bv = *(const float4*)&bet[t << 2];
    size_t base = (size_t)row * Dc + (t << 2);
    *(__half2*)&g_lnh[base]     = __floats2half2_rn(dx * inv * gv.x + bv.x, dy * inv * gv.y + bv.y);
    *(__half2*)&g_lnh[base + 2] = __floats2half2_rn(dz * inv * gv.z + bv.z, dw * inv * gv.w + bv.w);
}

// ---------------------------------------------------------------------------
extern "C" void kernel_launch(void* const* d_in, const int* in_sizes, int n_in,
                              void* d_out, int out_size)
{
    const float* x      = (const float*)d_in[0];
    const float* gumbel = (const float*)d_in[1];
    const float* Wx     = (const float*)d_in[2];
    const float* bx     = (const float*)d_in[3];
    const float* tw1    = (const float*)d_in[4];
    const float* tb1    = (const float*)d_in[5];
    const float* tw2    = (const float*)d_in[6];
    const float* tb2    = (const float*)d_in[7];
    const float* bias   = (const float*)d_in[8];
    const float* Wsl    = (const float*)d_in[9];
    const float* bsl    = (const float*)d_in[10];
    const float* Wq     = (const float*)d_in[11];
    const float* Wk     = (const float*)d_in[12];
    const float* Wv     = (const float*)d_in[13];
    const float* Wp     = (const float*)d_in[14];
    const float* bp     = (const float*)d_in[15];
    const float* ln2g   = (const float*)d_in[16];
    const float* ln2b   = (const float*)d_in[17];
    const float* W1     = (const float*)d_in[18];
    const float* b1     = (const float*)d_in[19];
    const float* W2     = (const float*)d_in[20];
    const float* b2     = (const float*)d_in[21];
    float* out = (float*)d_out;

    float *o2;
    __half *xh, *xmh, *yh, *lnh, *midh, *bth, *tw1T, *wslT;
    cudaGetSymbolAddress((void**)&o2,   g_o2);
    cudaGetSymbolAddress((void**)&xh,   g_xh);
    cudaGetSymbolAddress((void**)&xmh,  g_xmh);
    cudaGetSymbolAddress((void**)&yh,   g_yh);
    cudaGetSymbolAddress((void**)&lnh,  g_lnh);
    cudaGetSymbolAddress((void**)&midh, g_midh);
    cudaGetSymbolAddress((void**)&bth,  g_bth);
    cudaGetSymbolAddress((void**)&tw1T, g_tw1T);
    cudaGetSymbolAddress((void**)&wslT, g_wslT);

    cudaFuncSetAttribute((const void*)gemm_h16<0,__half>, cudaFuncAttributeMaxDynamicSharedMemorySize, GEMM_SMEM);
    cudaFuncSetAttribute((const void*)gemm_h16<1,float>,  cudaFuncAttributeMaxDynamicSharedMemorySize, GEMM_SMEM);
    cudaFuncSetAttribute((const void*)gemm_h16<2,__half>, cudaFuncAttributeMaxDynamicSharedMemorySize, GEMM_SMEM);
    cudaFuncSetAttribute((const void*)slice_attn,         cudaFuncAttributeMaxDynamicSharedMemorySize, SA_SMEM);

    // 0. conversions / transposes
    convert_f2h<<<(Mrows*(size_t)Dc)/2048, 256>>>(x, xh);
    dim3 tb32(32, 8);
    transpose_k<<<dim3(Dc/32,  Dc/32),  tb32>>>(Wx, bth + BT_WX, Dc,   Dc);
    transpose_k<<<dim3(Dc/32,  Dc/32),  tb32>>>(Wp, bth + BT_WP, Dc,   Dc);
    transpose_k<<<dim3(HIDc/32, Dc/32), tb32>>>(W1, bth + BT_W1, Dc,   HIDc);
    transpose_k<<<dim3(Dc/32, HIDc/32), tb32>>>(W2, bth + BT_W2, HIDc, Dc);
    transpose_k<<<dim3(2, 2), tb32>>>(tw1, tw1T, 64, 64);
    transpose_k<<<dim3(2, 2), tb32>>>(Wsl, wslT, 64, 64);

    // 1. xm = x @ Wx + bx  (fp16 out)
    gemm_h16<0,__half><<<dim3(Dc/128, Mrows/128), 256, GEMM_SMEM>>>(xh, bth + BT_WX, bx, nullptr, xmh, Dc, Dc);
    // 2. router (tensor cores) -> g_swh
    router_mma<<<MH/128, 256>>>(tb1, tw2, tb2, bias, bsl, gumbel);
    // 3. dispatch (tensor cores)
    dispatch_mma<<<dim3(Bc*Hc, SEGc), 256>>>();
    // 4. reduce + slice attention -> g_osth
    slice_attn<<<Bc*Hc, 256, SA_SMEM>>>(Wq, Wk, Wv);
    // 5. scatter (tensor cores) -> g_yh
    scatter_mma<<<Bc*Hc*64, 256>>>();
    // 6. o2 = y @ Wp + bp + x
    gemm_h16<1,float><<<dim3(Dc/128, Mrows/128), 256, GEMM_SMEM>>>(yh, bth + BT_WP, bp, x, o2, Dc, Dc);
    // 7. layernorm (fp16 out)
    ln_k<<<Mrows, 128>>>(ln2g, ln2b);
    // 8. mid = gelu(ln @ W1 + b1)  (fp16 out)
    gemm_h16<2,__half><<<dim3(HIDc/128, Mrows/128), 256, GEMM_SMEM>>>(lnh, bth + BT_W1, b1, nullptr, midh, Dc, HIDc);
    // 9. out = mid @ W2 + b2 + x
    gemm_h16<1,float><<<dim3(Dc/128, Mrows/128), 256, GEMM_SMEM>>>(midh, bth + BT_W2, b2, x, out, HIDc, Dc);
}